// round 1
// baseline (speedup 1.0000x reference)
#include <cuda_runtime.h>
#include <math.h>

#define N_NODES 50000
#define E_EDGES 800000
#define F_INPUT 128
#define HDIM    256
#define C_OUT   112
#define L_LAYERS 8
#define BN_EPS  1e-5f

// ---------------- scratch (device globals; no allocations anywhere) --------
__device__ float g_h[N_NODES * HDIM];        // current node features
__device__ float g_t[N_NODES * HDIM];        // post-linear features (message source)
__device__ float g_acc[N_NODES * HDIM];      // weighted residual accumulator
__device__ float g_logits[N_NODES * C_OUT];  // pre-logsoftmax output
__device__ float g_dinv1[N_NODES];
__device__ float g_dinv2[N_NODES];
__device__ float g_deg[N_NODES];
__device__ float g_sum[HDIM];
__device__ float g_sumsq[HDIM];
__device__ float g_w[L_LAYERS];              // softmax(layer_w)

// ---------------- degree / normalization ----------------------------------
__global__ void deg_init_kernel(float* deg) {
    int i = blockIdx.x * blockDim.x + threadIdx.x;
    if (i < N_NODES) deg[i] = 1.0f;  // self loop
}

__global__ void deg_accum_kernel(const int* __restrict__ tgt, float* deg) {
    int i = blockIdx.x * blockDim.x + threadIdx.x;
    if (i < E_EDGES) atomicAdd(&deg[tgt[i]], 1.0f);
}

__global__ void dinv_kernel(const float* __restrict__ deg, float* dinv) {
    int i = blockIdx.x * blockDim.x + threadIdx.x;
    if (i < N_NODES) dinv[i] = rsqrtf(deg[i]);  // deg >= 1 always
}

// ---------------- softmax over the 8 layer weights -------------------------
__global__ void softmax_w_kernel(const float* __restrict__ lw, float* w) {
    float m = -1e30f;
    for (int i = 0; i < L_LAYERS; i++) m = fmaxf(m, lw[i]);
    float s = 0.f;
    for (int i = 0; i < L_LAYERS; i++) s += expf(lw[i] - m);
    for (int i = 0; i < L_LAYERS; i++) w[i] = expf(lw[i] - m) / s;
}

// ---------------- generic FP32 GEMM: C[M,Nc] = A[M,K] @ B[K,Nc] + bias -----
// 64x64 block tile, 4x4 microtile, BK=16. K must be a multiple of 16.
__global__ void gemm_bias_kernel(const float* __restrict__ A,
                                 const float* __restrict__ B,
                                 const float* __restrict__ bias,
                                 float* __restrict__ C,
                                 int M, int Nc, int K) {
    __shared__ float As[16][65];
    __shared__ float Bs[16][65];
    int tid  = threadIdx.x;           // 0..255
    int tCol = tid & 15;
    int tRow = tid >> 4;
    int brow = blockIdx.y * 64;
    int bcol = blockIdx.x * 64;

    float acc[4][4];
#pragma unroll
    for (int i = 0; i < 4; i++)
#pragma unroll
        for (int j = 0; j < 4; j++) acc[i][j] = 0.f;

    for (int k0 = 0; k0 < K; k0 += 16) {
#pragma unroll
        for (int i = tid; i < 64 * 16; i += 256) {
            int k = i & 15, m = i >> 4;
            int gm = brow + m;
            As[k][m] = (gm < M) ? A[(size_t)gm * K + k0 + k] : 0.f;
        }
#pragma unroll
        for (int i = tid; i < 16 * 64; i += 256) {
            int k = i >> 6, n = i & 63;
            int gn = bcol + n;
            Bs[k][n] = (gn < Nc) ? B[(size_t)(k0 + k) * Nc + gn] : 0.f;
        }
        __syncthreads();
#pragma unroll
        for (int k = 0; k < 16; k++) {
            float a[4], b[4];
#pragma unroll
            for (int i = 0; i < 4; i++) a[i] = As[k][tRow * 4 + i];
#pragma unroll
            for (int j = 0; j < 4; j++) b[j] = Bs[k][tCol * 4 + j];
#pragma unroll
            for (int i = 0; i < 4; i++)
#pragma unroll
                for (int j = 0; j < 4; j++) acc[i][j] = fmaf(a[i], b[j], acc[i][j]);
        }
        __syncthreads();
    }

#pragma unroll
    for (int i = 0; i < 4; i++) {
        int gm = brow + tRow * 4 + i;
        if (gm >= M) continue;
#pragma unroll
        for (int j = 0; j < 4; j++) {
            int gn = bcol + tCol * 4 + j;
            if (gn < Nc) C[(size_t)gm * Nc + gn] = acc[i][j] + bias[gn];
        }
    }
}

// ---------------- self-loop initializer: h[v] = t[v] * dinv[v]^2 -----------
__global__ void selfloop_kernel(const float* __restrict__ t,
                                const float* __restrict__ dinv,
                                float* __restrict__ h) {
    int idx = blockIdx.x * blockDim.x + threadIdx.x;
    if (idx < N_NODES * HDIM) {
        int v = idx >> 8;  // HDIM = 256
        float d = dinv[v];
        h[idx] = t[idx] * d * d;
    }
}

// ---------------- edge scatter: h[tgt] += t[src] * dinv[src]*dinv[tgt] -----
// One warp per edge; float4 gather; atomicAdd scatter.
__global__ void scatter_kernel(const int* __restrict__ src,
                               const int* __restrict__ tgt,
                               const float* __restrict__ dinv,
                               const float* __restrict__ t,
                               float* __restrict__ h) {
    int gw   = (blockIdx.x * blockDim.x + threadIdx.x) >> 5;
    int lane = threadIdx.x & 31;
    if (gw >= E_EDGES) return;
    int s = src[gw];
    int d = tgt[gw];
    float nrm = dinv[s] * dinv[d];
    const float4* trow = (const float4*)(t + (size_t)s * HDIM);
    float* hrow = h + (size_t)d * HDIM;
#pragma unroll
    for (int i = 0; i < 2; i++) {
        int q = lane + 32 * i;      // 64 float4 per row
        float4 v = trow[q];
        int f = q * 4;
        atomicAdd(hrow + f + 0, v.x * nrm);
        atomicAdd(hrow + f + 1, v.y * nrm);
        atomicAdd(hrow + f + 2, v.z * nrm);
        atomicAdd(hrow + f + 3, v.w * nrm);
    }
}

// ---------------- BN statistics --------------------------------------------
__global__ void zero_stats_kernel(float* sum, float* sumsq) {
    int t = threadIdx.x;
    sum[t] = 0.f;
    sumsq[t] = 0.f;
}

__global__ void bn_stats_kernel(const float* __restrict__ h,
                                float* sum, float* sumsq) {
    int col = threadIdx.x;  // 256 threads = 256 columns
    float s = 0.f, s2 = 0.f;
    for (int r = blockIdx.x; r < N_NODES; r += gridDim.x) {
        float v = h[(size_t)r * HDIM + col];
        s += v;
        s2 += v * v;
    }
    atomicAdd(&sum[col], s);
    atomicAdd(&sumsq[col], s2);
}

// ---------------- BN apply + ReLU + weighted residual ----------------------
__global__ void bn_apply_kernel(float* __restrict__ h,
                                float* __restrict__ acc,
                                const float* __restrict__ sum,
                                const float* __restrict__ sumsq,
                                const float* __restrict__ gamma,
                                const float* __restrict__ beta,
                                const float* __restrict__ w, int layer) {
    int idx = blockIdx.x * blockDim.x + threadIdx.x;
    if (idx >= N_NODES * HDIM) return;
    int f = idx & 255;
    const float invN = 1.0f / (float)N_NODES;
    float mu  = sum[f] * invN;
    float var = sumsq[f] * invN - mu * mu;
    float v = (h[idx] - mu) * rsqrtf(var + BN_EPS) * gamma[f] + beta[f];
    v = fmaxf(v, 0.f);
    h[idx] = v;
    acc[idx] += w[layer] * v;
}

__global__ void zero_acc_kernel(float* acc) {
    int idx = blockIdx.x * blockDim.x + threadIdx.x;
    if (idx < N_NODES * HDIM) acc[idx] = 0.f;
}

// ---------------- log-softmax over C=112 classes, one warp per row ---------
__global__ void logsoftmax_kernel(const float* __restrict__ logits,
                                  float* __restrict__ out) {
    int row  = blockIdx.x * 8 + (threadIdx.x >> 5);
    int lane = threadIdx.x & 31;
    if (row >= N_NODES) return;
    const float* lr = logits + (size_t)row * C_OUT;

    float vals[4];
    int cnt = 0;
    float m = -1e30f;
    for (int f = lane; f < C_OUT; f += 32) {
        vals[cnt] = lr[f];
        m = fmaxf(m, vals[cnt]);
        cnt++;
    }
#pragma unroll
    for (int off = 16; off >= 1; off >>= 1)
        m = fmaxf(m, __shfl_xor_sync(0xffffffffu, m, off));

    float s = 0.f;
    for (int i = 0; i < cnt; i++) s += expf(vals[i] - m);
#pragma unroll
    for (int off = 16; off >= 1; off >>= 1)
        s += __shfl_xor_sync(0xffffffffu, s, off);

    float lse = m + logf(s);
    cnt = 0;
    for (int f = lane; f < C_OUT; f += 32) {
        out[(size_t)row * C_OUT + f] = vals[cnt] - lse;
        cnt++;
    }
}

// ---------------- host launcher --------------------------------------------
extern "C" void kernel_launch(void* const* d_in, const int* in_sizes, int n_in,
                              void* d_out, int out_size) {
    const float* x       = (const float*)d_in[0];
    const int*   e1      = (const int*)  d_in[1];
    const int*   e2      = (const int*)  d_in[2];
    const float* in_W    = (const float*)d_in[3];
    const float* in_b    = (const float*)d_in[4];
    const float* convW   = (const float*)d_in[5];
    const float* convB   = (const float*)d_in[6];
    const float* bng     = (const float*)d_in[7];
    const float* bnb     = (const float*)d_in[8];
    const float* out_W   = (const float*)d_in[9];
    const float* out_b   = (const float*)d_in[10];
    const float* layer_w = (const float*)d_in[11];
    float* out = (float*)d_out;

    float *p_h, *p_t, *p_acc, *p_logits, *p_dinv1, *p_dinv2, *p_deg, *p_sum, *p_sumsq, *p_w;
    cudaGetSymbolAddress((void**)&p_h, g_h);
    cudaGetSymbolAddress((void**)&p_t, g_t);
    cudaGetSymbolAddress((void**)&p_acc, g_acc);
    cudaGetSymbolAddress((void**)&p_logits, g_logits);
    cudaGetSymbolAddress((void**)&p_dinv1, g_dinv1);
    cudaGetSymbolAddress((void**)&p_dinv2, g_dinv2);
    cudaGetSymbolAddress((void**)&p_deg, g_deg);
    cudaGetSymbolAddress((void**)&p_sum, g_sum);
    cudaGetSymbolAddress((void**)&p_sumsq, g_sumsq);
    cudaGetSymbolAddress((void**)&p_w, g_w);

    const int nThr = 256;
    const int nbN     = (N_NODES + nThr - 1) / nThr;           // 196
    const int nbE     = (E_EDGES + nThr - 1) / nThr;           // 3125
    const int nbNH    = (N_NODES * HDIM + nThr - 1) / nThr;    // 50000
    const int nbScat  = (E_EDGES * 32 + nThr - 1) / nThr;      // 100000 (warp/edge)
    const dim3 gemmH(HDIM / 64, (N_NODES + 63) / 64);          // (4, 782)
    const dim3 gemmC((C_OUT + 63) / 64, (N_NODES + 63) / 64);  // (2, 782)

    // adjacency 1 normalization
    deg_init_kernel<<<nbN, nThr>>>(p_deg);
    deg_accum_kernel<<<nbE, nThr>>>(e1 + E_EDGES, p_deg);
    dinv_kernel<<<nbN, nThr>>>(p_deg, p_dinv1);
    // adjacency 2 normalization
    deg_init_kernel<<<nbN, nThr>>>(p_deg);
    deg_accum_kernel<<<nbE, nThr>>>(e2 + E_EDGES, p_deg);
    dinv_kernel<<<nbN, nThr>>>(p_deg, p_dinv2);

    softmax_w_kernel<<<1, 1>>>(layer_w, p_w);
    zero_acc_kernel<<<nbNH, nThr>>>(p_acc);

    // input FC: h = x @ in_W + in_b   [N,128]x[128,256]
    gemm_bias_kernel<<<gemmH, nThr>>>(x, in_W, in_b, p_h, N_NODES, HDIM, F_INPUT);

    for (int l = 0; l < L_LAYERS; l++) {
        const int*   edges = (l < L_LAYERS / 2) ? e1 : e2;
        const float* dinv  = (l < L_LAYERS / 2) ? p_dinv1 : p_dinv2;

        // t = h @ convW[l] + convB[l]
        gemm_bias_kernel<<<gemmH, nThr>>>(p_h, convW + (size_t)l * HDIM * HDIM,
                                          convB + l * HDIM, p_t, N_NODES, HDIM, HDIM);
        // h = A_hat_norm @ t  (self-loop init + edge atomics)
        selfloop_kernel<<<nbNH, nThr>>>(p_t, dinv, p_h);
        scatter_kernel<<<nbScat, nThr>>>(edges, edges + E_EDGES, dinv, p_t, p_h);
        // BatchNorm + ReLU + residual
        zero_stats_kernel<<<1, HDIM>>>(p_sum, p_sumsq);
        bn_stats_kernel<<<512, HDIM>>>(p_h, p_sum, p_sumsq);
        bn_apply_kernel<<<nbNH, nThr>>>(p_h, p_acc, p_sum, p_sumsq,
                                        bng + l * HDIM, bnb + l * HDIM, p_w, l);
    }

    // output FC + log_softmax
    gemm_bias_kernel<<<gemmC, nThr>>>(p_acc, out_W, out_b, p_logits, N_NODES, C_OUT, HDIM);
    logsoftmax_kernel<<<(N_NODES + 7) / 8, nThr>>>(p_logits, out);
}

// round 2
// speedup vs baseline: 2.1852x; 2.1852x over previous
#include <cuda_runtime.h>
#include <math.h>

#define N_NODES 50000
#define E_EDGES 800000
#define F_INPUT 128
#define HDIM    256
#define C_OUT   112
#define L_LAYERS 8
#define BN_EPS  1e-5f

// ---------------- scratch (device globals; no allocations anywhere) --------
__device__ float g_h[N_NODES * HDIM];        // current node features
__device__ float g_t[N_NODES * HDIM];        // post-linear features (message source)
__device__ float g_acc[N_NODES * HDIM];      // weighted residual accumulator
__device__ float g_logits[N_NODES * C_OUT];  // pre-logsoftmax output
__device__ float g_dinv1[N_NODES];
__device__ float g_dinv2[N_NODES];
__device__ float g_deg[N_NODES];
__device__ float g_sum[HDIM];
__device__ float g_sumsq[HDIM];
__device__ float g_w[L_LAYERS];              // softmax(layer_w)

// ---------------- degree / normalization ----------------------------------
__global__ void deg_init_kernel(float* deg) {
    int i = blockIdx.x * blockDim.x + threadIdx.x;
    if (i < N_NODES) deg[i] = 1.0f;  // self loop
}

__global__ void deg_accum_kernel(const int* __restrict__ tgt, float* deg) {
    int i = blockIdx.x * blockDim.x + threadIdx.x;
    if (i < E_EDGES) atomicAdd(&deg[tgt[i]], 1.0f);
}

__global__ void dinv_kernel(const float* __restrict__ deg, float* dinv) {
    int i = blockIdx.x * blockDim.x + threadIdx.x;
    if (i < N_NODES) dinv[i] = rsqrtf(deg[i]);  // deg >= 1 always
}

// ---------------- softmax over the 8 layer weights -------------------------
__global__ void softmax_w_kernel(const float* __restrict__ lw, float* w) {
    float m = -1e30f;
    for (int i = 0; i < L_LAYERS; i++) m = fmaxf(m, lw[i]);
    float s = 0.f;
    for (int i = 0; i < L_LAYERS; i++) s += expf(lw[i] - m);
    for (int i = 0; i < L_LAYERS; i++) w[i] = expf(lw[i] - m) / s;
}

// ---------------- FP32 GEMM: C[M,Nc] = A[M,K] @ B[K,Nc] + bias -------------
// 128x128 block tile, 8x8 microtile (split halves), BK=16, double-buffered.
// K must be a multiple of 16; Nc a multiple of 4.
#define BM 128
#define BN 128
#define BK 16

__global__ __launch_bounds__(256, 2)
void gemm_bias_kernel(const float* __restrict__ A,
                      const float* __restrict__ B,
                      const float* __restrict__ bias,
                      float* __restrict__ C,
                      int M, int Nc, int K) {
    __shared__ float As[2][BK][BM + 4];   // row len 132 floats (16B multiple)
    __shared__ float Bs[2][BK][BN];

    const int tid  = threadIdx.x;          // 0..255
    const int tRow = tid >> 4;             // 0..15
    const int tCol = tid & 15;             // 0..15
    const int brow = blockIdx.y * BM;
    const int bcol = blockIdx.x * BN;

    // A staging: 512 float4 per tile, 2 per thread.  f4id -> m = f4id>>2, kq = f4id&3
    const int am0 = tid >> 2;                    // 0..63
    const int am1 = (tid + 256) >> 2;            // 64..127
    const int ak  = (tid & 3) * 4;               // 0,4,8,12
    const int arow0 = min(brow + am0, M - 1);
    const int arow1 = min(brow + am1, M - 1);

    // B staging: f4id -> k = f4id>>5, n4 = (f4id&31)*4
    const int bk0 = tid >> 5;                    // 0..7
    const int bk1 = bk0 + 8;                     // 8..15
    const int bn  = (tid & 31) * 4;              // 0..124
    const bool bok = (bcol + bn + 3) < Nc;       // Nc multiple of 4
    const int bcl  = bok ? (bcol + bn) : 0;

    float acc[8][8];
#pragma unroll
    for (int i = 0; i < 8; i++)
#pragma unroll
        for (int j = 0; j < 8; j++) acc[i][j] = 0.f;

    float4 aR0, aR1, bR0, bR1;
    const float4 z4 = make_float4(0.f, 0.f, 0.f, 0.f);

    // preload tile 0
    aR0 = *(const float4*)(A + (size_t)arow0 * K + ak);
    aR1 = *(const float4*)(A + (size_t)arow1 * K + ak);
    bR0 = bok ? *(const float4*)(B + (size_t)bk0 * Nc + bcl) : z4;
    bR1 = bok ? *(const float4*)(B + (size_t)bk1 * Nc + bcl) : z4;
    {
        As[0][ak + 0][am0] = aR0.x; As[0][ak + 1][am0] = aR0.y;
        As[0][ak + 2][am0] = aR0.z; As[0][ak + 3][am0] = aR0.w;
        As[0][ak + 0][am1] = aR1.x; As[0][ak + 1][am1] = aR1.y;
        As[0][ak + 2][am1] = aR1.z; As[0][ak + 3][am1] = aR1.w;
        *(float4*)&Bs[0][bk0][bn] = bR0;
        *(float4*)&Bs[0][bk1][bn] = bR1;
    }
    __syncthreads();

    const int nt = K / BK;
    for (int kt = 0; kt < nt; kt++) {
        const int buf = kt & 1;
        const int nxt = kt + 1;
        if (nxt < nt) {
            const int k0 = nxt * BK;
            aR0 = *(const float4*)(A + (size_t)arow0 * K + k0 + ak);
            aR1 = *(const float4*)(A + (size_t)arow1 * K + k0 + ak);
            bR0 = bok ? *(const float4*)(B + (size_t)(k0 + bk0) * Nc + bcl) : z4;
            bR1 = bok ? *(const float4*)(B + (size_t)(k0 + bk1) * Nc + bcl) : z4;
        }
#pragma unroll
        for (int k = 0; k < BK; k++) {
            float4 a0 = *(const float4*)&As[buf][k][tRow * 4];
            float4 a1 = *(const float4*)&As[buf][k][64 + tRow * 4];
            float4 b0 = *(const float4*)&Bs[buf][k][tCol * 4];
            float4 b1 = *(const float4*)&Bs[buf][k][64 + tCol * 4];
            float a[8] = {a0.x, a0.y, a0.z, a0.w, a1.x, a1.y, a1.z, a1.w};
            float b[8] = {b0.x, b0.y, b0.z, b0.w, b1.x, b1.y, b1.z, b1.w};
#pragma unroll
            for (int i = 0; i < 8; i++)
#pragma unroll
                for (int j = 0; j < 8; j++)
                    acc[i][j] = fmaf(a[i], b[j], acc[i][j]);
        }
        if (nxt < nt) {
            const int nb = nxt & 1;
            As[nb][ak + 0][am0] = aR0.x; As[nb][ak + 1][am0] = aR0.y;
            As[nb][ak + 2][am0] = aR0.z; As[nb][ak + 3][am0] = aR0.w;
            As[nb][ak + 0][am1] = aR1.x; As[nb][ak + 1][am1] = aR1.y;
            As[nb][ak + 2][am1] = aR1.z; As[nb][ak + 3][am1] = aR1.w;
            *(float4*)&Bs[nb][bk0][bn] = bR0;
            *(float4*)&Bs[nb][bk1][bn] = bR1;
        }
        __syncthreads();
    }

    // epilogue: 2x2 half-blocks of 4x4, vectorized float4 stores
#pragma unroll
    for (int ih = 0; ih < 2; ih++) {
#pragma unroll
        for (int i = 0; i < 4; i++) {
            int r = brow + ih * 64 + tRow * 4 + i;
            if (r >= M) continue;
#pragma unroll
            for (int jh = 0; jh < 2; jh++) {
                int c = bcol + jh * 64 + tCol * 4;
                if (c + 3 < Nc) {
                    float4 o;
                    o.x = acc[ih * 4 + i][jh * 4 + 0] + bias[c + 0];
                    o.y = acc[ih * 4 + i][jh * 4 + 1] + bias[c + 1];
                    o.z = acc[ih * 4 + i][jh * 4 + 2] + bias[c + 2];
                    o.w = acc[ih * 4 + i][jh * 4 + 3] + bias[c + 3];
                    *(float4*)(C + (size_t)r * Nc + c) = o;
                }
            }
        }
    }
}

// ---------------- self-loop initializer: h[v] = t[v] * dinv[v]^2 -----------
__global__ void selfloop_kernel(const float* __restrict__ t,
                                const float* __restrict__ dinv,
                                float* __restrict__ h) {
    int idx = blockIdx.x * blockDim.x + threadIdx.x;
    if (idx < N_NODES * HDIM) {
        int v = idx >> 8;  // HDIM = 256
        float d = dinv[v];
        h[idx] = t[idx] * d * d;
    }
}

// ---------------- vectorized f32 global reduction --------------------------
__device__ __forceinline__ void red_add_v4(float* addr, float4 v) {
    asm volatile("red.global.add.v4.f32 [%0], {%1, %2, %3, %4};"
                 :: "l"(addr), "f"(v.x), "f"(v.y), "f"(v.z), "f"(v.w)
                 : "memory");
}

// ---------------- edge scatter: h[tgt] += t[src] * dinv[src]*dinv[tgt] -----
// One warp per edge; float4 gather; red.v4 scatter.
__global__ void scatter_kernel(const int* __restrict__ src,
                               const int* __restrict__ tgt,
                               const float* __restrict__ dinv,
                               const float* __restrict__ t,
                               float* __restrict__ h) {
    int gw   = (blockIdx.x * blockDim.x + threadIdx.x) >> 5;
    int lane = threadIdx.x & 31;
    if (gw >= E_EDGES) return;
    int s = __ldg(src + gw);
    int d = __ldg(tgt + gw);
    float nrm = dinv[s] * dinv[d];
    const float4* trow = (const float4*)(t + (size_t)s * HDIM);
    float* hrow = h + (size_t)d * HDIM;
#pragma unroll
    for (int i = 0; i < 2; i++) {
        int q = lane + 32 * i;      // 64 float4 per row
        float4 v = trow[q];
        float4 m = make_float4(v.x * nrm, v.y * nrm, v.z * nrm, v.w * nrm);
        red_add_v4(hrow + q * 4, m);
    }
}

// ---------------- BN statistics --------------------------------------------
__global__ void zero_stats_kernel(float* sum, float* sumsq) {
    int t = threadIdx.x;
    sum[t] = 0.f;
    sumsq[t] = 0.f;
}

__global__ void bn_stats_kernel(const float* __restrict__ h,
                                float* sum, float* sumsq) {
    int col = threadIdx.x;  // 256 threads = 256 columns
    float s = 0.f, s2 = 0.f;
    for (int r = blockIdx.x; r < N_NODES; r += gridDim.x) {
        float v = h[(size_t)r * HDIM + col];
        s += v;
        s2 += v * v;
    }
    atomicAdd(&sum[col], s);
    atomicAdd(&sumsq[col], s2);
}

// ---------------- BN apply + ReLU + weighted residual ----------------------
__global__ void bn_apply_kernel(float* __restrict__ h,
                                float* __restrict__ acc,
                                const float* __restrict__ sum,
                                const float* __restrict__ sumsq,
                                const float* __restrict__ gamma,
                                const float* __restrict__ beta,
                                const float* __restrict__ w, int layer) {
    int idx = blockIdx.x * blockDim.x + threadIdx.x;
    if (idx >= N_NODES * HDIM) return;
    int f = idx & 255;
    const float invN = 1.0f / (float)N_NODES;
    float mu  = sum[f] * invN;
    float var = sumsq[f] * invN - mu * mu;
    float v = (h[idx] - mu) * rsqrtf(var + BN_EPS) * gamma[f] + beta[f];
    v = fmaxf(v, 0.f);
    h[idx] = v;
    acc[idx] += w[layer] * v;
}

__global__ void zero_acc_kernel(float* acc) {
    int idx = blockIdx.x * blockDim.x + threadIdx.x;
    if (idx < N_NODES * HDIM) acc[idx] = 0.f;
}

// ---------------- log-softmax over C=112 classes, one warp per row ---------
__global__ void logsoftmax_kernel(const float* __restrict__ logits,
                                  float* __restrict__ out) {
    int row  = blockIdx.x * 8 + (threadIdx.x >> 5);
    int lane = threadIdx.x & 31;
    if (row >= N_NODES) return;
    const float* lr = logits + (size_t)row * C_OUT;

    float vals[4];
    int cnt = 0;
    float m = -1e30f;
    for (int f = lane; f < C_OUT; f += 32) {
        vals[cnt] = lr[f];
        m = fmaxf(m, vals[cnt]);
        cnt++;
    }
#pragma unroll
    for (int off = 16; off >= 1; off >>= 1)
        m = fmaxf(m, __shfl_xor_sync(0xffffffffu, m, off));

    float s = 0.f;
    for (int i = 0; i < cnt; i++) s += expf(vals[i] - m);
#pragma unroll
    for (int off = 16; off >= 1; off >>= 1)
        s += __shfl_xor_sync(0xffffffffu, s, off);

    float lse = m + logf(s);
    cnt = 0;
    for (int f = lane; f < C_OUT; f += 32) {
        out[(size_t)row * C_OUT + f] = vals[cnt] - lse;
        cnt++;
    }
}

// ---------------- host launcher --------------------------------------------
extern "C" void kernel_launch(void* const* d_in, const int* in_sizes, int n_in,
                              void* d_out, int out_size) {
    const float* x       = (const float*)d_in[0];
    const int*   e1      = (const int*)  d_in[1];
    const int*   e2      = (const int*)  d_in[2];
    const float* in_W    = (const float*)d_in[3];
    const float* in_b    = (const float*)d_in[4];
    const float* convW   = (const float*)d_in[5];
    const float* convB   = (const float*)d_in[6];
    const float* bng     = (const float*)d_in[7];
    const float* bnb     = (const float*)d_in[8];
    const float* out_W   = (const float*)d_in[9];
    const float* out_b   = (const float*)d_in[10];
    const float* layer_w = (const float*)d_in[11];
    float* out = (float*)d_out;

    float *p_h, *p_t, *p_acc, *p_logits, *p_dinv1, *p_dinv2, *p_deg, *p_sum, *p_sumsq, *p_w;
    cudaGetSymbolAddress((void**)&p_h, g_h);
    cudaGetSymbolAddress((void**)&p_t, g_t);
    cudaGetSymbolAddress((void**)&p_acc, g_acc);
    cudaGetSymbolAddress((void**)&p_logits, g_logits);
    cudaGetSymbolAddress((void**)&p_dinv1, g_dinv1);
    cudaGetSymbolAddress((void**)&p_dinv2, g_dinv2);
    cudaGetSymbolAddress((void**)&p_deg, g_deg);
    cudaGetSymbolAddress((void**)&p_sum, g_sum);
    cudaGetSymbolAddress((void**)&p_sumsq, g_sumsq);
    cudaGetSymbolAddress((void**)&p_w, g_w);

    const int nThr = 256;
    const int nbN     = (N_NODES + nThr - 1) / nThr;           // 196
    const int nbE     = (E_EDGES + nThr - 1) / nThr;           // 3125
    const int nbNH    = (N_NODES * HDIM + nThr - 1) / nThr;    // 50000
    const int nbScat  = (E_EDGES * 32 + nThr - 1) / nThr;      // warp per edge
    const dim3 gemmH(HDIM / BN, (N_NODES + BM - 1) / BM);      // (2, 391)
    const dim3 gemmC(1, (N_NODES + BM - 1) / BM);              // (1, 391)

    // adjacency 1 normalization
    deg_init_kernel<<<nbN, nThr>>>(p_deg);
    deg_accum_kernel<<<nbE, nThr>>>(e1 + E_EDGES, p_deg);
    dinv_kernel<<<nbN, nThr>>>(p_deg, p_dinv1);
    // adjacency 2 normalization
    deg_init_kernel<<<nbN, nThr>>>(p_deg);
    deg_accum_kernel<<<nbE, nThr>>>(e2 + E_EDGES, p_deg);
    dinv_kernel<<<nbN, nThr>>>(p_deg, p_dinv2);

    softmax_w_kernel<<<1, 1>>>(layer_w, p_w);
    zero_acc_kernel<<<nbNH, nThr>>>(p_acc);

    // input FC: h = x @ in_W + in_b   [N,128]x[128,256]
    gemm_bias_kernel<<<gemmH, nThr>>>(x, in_W, in_b, p_h, N_NODES, HDIM, F_INPUT);

    for (int l = 0; l < L_LAYERS; l++) {
        const int*   edges = (l < L_LAYERS / 2) ? e1 : e2;
        const float* dinv  = (l < L_LAYERS / 2) ? p_dinv1 : p_dinv2;

        // t = h @ convW[l] + convB[l]
        gemm_bias_kernel<<<gemmH, nThr>>>(p_h, convW + (size_t)l * HDIM * HDIM,
                                          convB + l * HDIM, p_t, N_NODES, HDIM, HDIM);
        // h = A_hat_norm @ t  (self-loop init + vectorized edge reductions)
        selfloop_kernel<<<nbNH, nThr>>>(p_t, dinv, p_h);
        scatter_kernel<<<nbScat, nThr>>>(edges, edges + E_EDGES, dinv, p_t, p_h);
        // BatchNorm + ReLU + residual
        zero_stats_kernel<<<1, HDIM>>>(p_sum, p_sumsq);
        bn_stats_kernel<<<512, HDIM>>>(p_h, p_sum, p_sumsq);
        bn_apply_kernel<<<nbNH, nThr>>>(p_h, p_acc, p_sum, p_sumsq,
                                        bng + l * HDIM, bnb + l * HDIM, p_w, l);
    }

    // output FC + log_softmax
    gemm_bias_kernel<<<gemmC, nThr>>>(p_acc, out_W, out_b, p_logits, N_NODES, C_OUT, HDIM);
    logsoftmax_kernel<<<(N_NODES + 7) / 8, nThr>>>(p_logits, out);
}

// round 3
// speedup vs baseline: 3.2233x; 1.4751x over previous
#include <cuda_runtime.h>
#include <math.h>

#define N_NODES 50000
#define E_EDGES 800000
#define F_INPUT 128
#define HDIM    256
#define C_OUT   112
#define L_LAYERS 8
#define BN_EPS  1e-5f

// ---------------- scratch (device globals; no allocations anywhere) --------
__device__ float g_h[N_NODES * HDIM];
__device__ float g_t[N_NODES * HDIM];        // t' = (h@W+b) * dinv[row]
__device__ float g_acc[N_NODES * HDIM];
__device__ float g_logits[N_NODES * C_OUT];
__device__ float g_dinv1[N_NODES];
__device__ float g_dinv2[N_NODES];
__device__ float g_sum[HDIM];
__device__ float g_sumsq[HDIM];
__device__ float g_w[L_LAYERS];
// CSR structures (built per launch by counting sort)
__device__ int g_cnt[N_NODES];
__device__ int g_rp1[N_NODES + 1];
__device__ int g_rp2[N_NODES + 1];
__device__ int g_cur[N_NODES];
__device__ int g_csr1[E_EDGES];
__device__ int g_csr2[E_EDGES];

// ---------------- f32x2 packed helpers -------------------------------------
__device__ __forceinline__ unsigned long long pk2(float lo, float hi) {
    unsigned long long r;
    asm("mov.b64 %0, {%1, %2};" : "=l"(r) : "f"(lo), "f"(hi));
    return r;
}
__device__ __forceinline__ void upk2(float& lo, float& hi, unsigned long long v) {
    asm("mov.b64 {%0, %1}, %2;" : "=f"(lo), "=f"(hi) : "l"(v));
}
__device__ __forceinline__ void ffma2(unsigned long long& d,
                                      unsigned long long a, unsigned long long b) {
    asm("fma.rn.f32x2 %0, %1, %2, %0;" : "+l"(d) : "l"(a), "l"(b));
}

// ---------------- CSR build -------------------------------------------------
__global__ void zero_cnt_kernel(int* cnt) {
    int i = blockIdx.x * blockDim.x + threadIdx.x;
    if (i < N_NODES) cnt[i] = 0;
}

__global__ void hist_kernel(const int* __restrict__ tgt, int* cnt) {
    int i = blockIdx.x * blockDim.x + threadIdx.x;
    if (i < E_EDGES) atomicAdd(&cnt[tgt[i]], 1);
}

// single-block exclusive scan over 50000 counts -> rowptr (incl rowptr[N]=E)
__global__ void scan_kernel(const int* __restrict__ cnt, int* rowptr) {
    __shared__ int s[1024];
    const int T = 1024;
    const int CH = (N_NODES + T - 1) / T;  // 49
    int t = threadIdx.x;
    int base = t * CH;
    int loc = 0;
    for (int i = 0; i < CH; i++) {
        int idx = base + i;
        if (idx < N_NODES) loc += cnt[idx];
    }
    s[t] = loc;
    __syncthreads();
    // Hillis-Steele inclusive scan
    for (int off = 1; off < T; off <<= 1) {
        int v = (t >= off) ? s[t - off] : 0;
        __syncthreads();
        s[t] += v;
        __syncthreads();
    }
    int run = s[t] - loc;  // exclusive prefix for this chunk
    for (int i = 0; i < CH; i++) {
        int idx = base + i;
        if (idx < N_NODES) {
            rowptr[idx] = run;
            run += cnt[idx];
        }
    }
    if (t == T - 1) rowptr[N_NODES] = run;
}

__global__ void dinv_from_rp_kernel(const int* __restrict__ rowptr, float* dinv) {
    int i = blockIdx.x * blockDim.x + threadIdx.x;
    if (i < N_NODES)
        dinv[i] = rsqrtf((float)(rowptr[i + 1] - rowptr[i]) + 1.0f);  // +1 self loop
}

__global__ void cursor_copy_kernel(const int* __restrict__ rowptr, int* cur) {
    int i = blockIdx.x * blockDim.x + threadIdx.x;
    if (i < N_NODES) cur[i] = rowptr[i];
}

__global__ void fill_kernel(const int* __restrict__ src, const int* __restrict__ tgt,
                            int* cur, int* csr) {
    int i = blockIdx.x * blockDim.x + threadIdx.x;
    if (i < E_EDGES) {
        int pos = atomicAdd(&cur[tgt[i]], 1);
        csr[pos] = src[i];
    }
}

// ---------------- softmax over the 8 layer weights -------------------------
__global__ void softmax_w_kernel(const float* __restrict__ lw, float* w) {
    float m = -1e30f;
    for (int i = 0; i < L_LAYERS; i++) m = fmaxf(m, lw[i]);
    float s = 0.f;
    for (int i = 0; i < L_LAYERS; i++) s += expf(lw[i] - m);
    for (int i = 0; i < L_LAYERS; i++) w[i] = expf(lw[i] - m) / s;
}

// ---------------- FP32 GEMM via FFMA2 (f32x2): C = A@B + bias, opt *dinv ---
#define BM 128
#define BN 128
#define BK 16

__global__ __launch_bounds__(256, 2)
void gemm_bias_kernel(const float* __restrict__ A,
                      const float* __restrict__ B,
                      const float* __restrict__ bias,
                      const float* __restrict__ dinv,   // nullptr -> no row scale
                      float* __restrict__ C,
                      int M, int Nc, int K) {
    __shared__ float As[2][BK][BM + 4];
    __shared__ float Bs[2][BK][BN];

    const int tid  = threadIdx.x;
    const int tRow = tid >> 4;
    const int tCol = tid & 15;
    const int brow = blockIdx.y * BM;
    const int bcol = blockIdx.x * BN;

    const int am0 = tid >> 2;
    const int am1 = (tid + 256) >> 2;
    const int ak  = (tid & 3) * 4;
    const int arow0 = min(brow + am0, M - 1);
    const int arow1 = min(brow + am1, M - 1);

    const int bk0 = tid >> 5;
    const int bk1 = bk0 + 8;
    const int bnx = (tid & 31) * 4;
    const bool bok = (bcol + bnx + 3) < Nc;
    const int bcl  = bok ? (bcol + bnx) : 0;

    // accumulators: 8 rows x 4 f32x2 pairs (cols packed)
    unsigned long long acc[8][4];
#pragma unroll
    for (int i = 0; i < 8; i++)
#pragma unroll
        for (int j = 0; j < 4; j++) acc[i][j] = 0ull;

    float4 aR0, aR1, bR0, bR1;
    const float4 z4 = make_float4(0.f, 0.f, 0.f, 0.f);

    aR0 = *(const float4*)(A + (size_t)arow0 * K + ak);
    aR1 = *(const float4*)(A + (size_t)arow1 * K + ak);
    bR0 = bok ? *(const float4*)(B + (size_t)bk0 * Nc + bcl) : z4;
    bR1 = bok ? *(const float4*)(B + (size_t)bk1 * Nc + bcl) : z4;
    {
        As[0][ak + 0][am0] = aR0.x; As[0][ak + 1][am0] = aR0.y;
        As[0][ak + 2][am0] = aR0.z; As[0][ak + 3][am0] = aR0.w;
        As[0][ak + 0][am1] = aR1.x; As[0][ak + 1][am1] = aR1.y;
        As[0][ak + 2][am1] = aR1.z; As[0][ak + 3][am1] = aR1.w;
        *(float4*)&Bs[0][bk0][bnx] = bR0;
        *(float4*)&Bs[0][bk1][bnx] = bR1;
    }
    __syncthreads();

    const int nt = K / BK;
    for (int kt = 0; kt < nt; kt++) {
        const int buf = kt & 1;
        const int nxt = kt + 1;
        if (nxt < nt) {
            const int k0 = nxt * BK;
            aR0 = *(const float4*)(A + (size_t)arow0 * K + k0 + ak);
            aR1 = *(const float4*)(A + (size_t)arow1 * K + k0 + ak);
            bR0 = bok ? *(const float4*)(B + (size_t)(k0 + bk0) * Nc + bcl) : z4;
            bR1 = bok ? *(const float4*)(B + (size_t)(k0 + bk1) * Nc + bcl) : z4;
        }
#pragma unroll
        for (int k = 0; k < BK; k++) {
            float4 a0 = *(const float4*)&As[buf][k][tRow * 4];
            float4 a1 = *(const float4*)&As[buf][k][64 + tRow * 4];
            float4 b0 = *(const float4*)&Bs[buf][k][tCol * 4];
            float4 b1 = *(const float4*)&Bs[buf][k][64 + tCol * 4];
            unsigned long long bb[4] = {pk2(b0.x, b0.y), pk2(b0.z, b0.w),
                                        pk2(b1.x, b1.y), pk2(b1.z, b1.w)};
            float av[8] = {a0.x, a0.y, a0.z, a0.w, a1.x, a1.y, a1.z, a1.w};
#pragma unroll
            for (int i = 0; i < 8; i++) {
                unsigned long long ap = pk2(av[i], av[i]);
#pragma unroll
                for (int j = 0; j < 4; j++) ffma2(acc[i][j], ap, bb[j]);
            }
        }
        if (nxt < nt) {
            const int nb = nxt & 1;
            As[nb][ak + 0][am0] = aR0.x; As[nb][ak + 1][am0] = aR0.y;
            As[nb][ak + 2][am0] = aR0.z; As[nb][ak + 3][am0] = aR0.w;
            As[nb][ak + 0][am1] = aR1.x; As[nb][ak + 1][am1] = aR1.y;
            As[nb][ak + 2][am1] = aR1.z; As[nb][ak + 3][am1] = aR1.w;
            *(float4*)&Bs[nb][bk0][bnx] = bR0;
            *(float4*)&Bs[nb][bk1][bnx] = bR1;
        }
        __syncthreads();
    }

#pragma unroll
    for (int ih = 0; ih < 2; ih++) {
#pragma unroll
        for (int i = 0; i < 4; i++) {
            int r = brow + ih * 64 + tRow * 4 + i;
            if (r >= M) continue;
            float ds = dinv ? dinv[r] : 1.0f;
#pragma unroll
            for (int jh = 0; jh < 2; jh++) {
                int c = bcol + jh * 64 + tCol * 4;
                if (c + 3 < Nc) {
                    float4 o;
                    float e0, e1, e2, e3;
                    upk2(e0, e1, acc[ih * 4 + i][jh * 2 + 0]);
                    upk2(e2, e3, acc[ih * 4 + i][jh * 2 + 1]);
                    o.x = (e0 + bias[c + 0]) * ds;
                    o.y = (e1 + bias[c + 1]) * ds;
                    o.z = (e2 + bias[c + 2]) * ds;
                    o.w = (e3 + bias[c + 3]) * ds;
                    *(float4*)(C + (size_t)r * Nc + c) = o;
                }
            }
        }
    }
}

// ---------------- CSR aggregation + fused BN stats --------------------------
// h[v] = dinv[v] * (t'[v] + sum_{s in N_in(v)} t'[s]);  stats over written h.
// One warp per node (grid-stride). 8 warps / 256-thr block.
__global__ __launch_bounds__(256)
void agg_kernel(const int* __restrict__ rowptr, const int* __restrict__ csr,
                const float* __restrict__ dinv, const float* __restrict__ tp,
                float* __restrict__ h, float* gsum, float* gsq) {
    __shared__ float s_sum[HDIM];
    __shared__ float s_sq[HDIM];
    int tid  = threadIdx.x;
    int lane = tid & 31;
    int warp = tid >> 5;
    int gw   = blockIdx.x * 8 + warp;
    int nw   = gridDim.x * 8;

    s_sum[tid] = 0.f;
    s_sq[tid]  = 0.f;

    float ssum[8], ssq[8];
#pragma unroll
    for (int i = 0; i < 8; i++) { ssum[i] = 0.f; ssq[i] = 0.f; }

    for (int v = gw; v < N_NODES; v += nw) {
        const float4* self = (const float4*)(tp + (size_t)v * HDIM);
        float4 a0 = self[lane];
        float4 a1 = self[lane + 32];
        int beg = rowptr[v], end = rowptr[v + 1];
        int e = beg;
        for (; e + 1 < end; e += 2) {
            int s0 = csr[e], s1 = csr[e + 1];
            const float4* r0 = (const float4*)(tp + (size_t)s0 * HDIM);
            const float4* r1 = (const float4*)(tp + (size_t)s1 * HDIM);
            float4 v00 = r0[lane], v01 = r0[lane + 32];
            float4 v10 = r1[lane], v11 = r1[lane + 32];
            a0.x += v00.x + v10.x; a0.y += v00.y + v10.y;
            a0.z += v00.z + v10.z; a0.w += v00.w + v10.w;
            a1.x += v01.x + v11.x; a1.y += v01.y + v11.y;
            a1.z += v01.z + v11.z; a1.w += v01.w + v11.w;
        }
        if (e < end) {
            int s0 = csr[e];
            const float4* r0 = (const float4*)(tp + (size_t)s0 * HDIM);
            float4 v00 = r0[lane], v01 = r0[lane + 32];
            a0.x += v00.x; a0.y += v00.y; a0.z += v00.z; a0.w += v00.w;
            a1.x += v01.x; a1.y += v01.y; a1.z += v01.z; a1.w += v01.w;
        }
        float dv = dinv[v];
        a0.x *= dv; a0.y *= dv; a0.z *= dv; a0.w *= dv;
        a1.x *= dv; a1.y *= dv; a1.z *= dv; a1.w *= dv;
        float4* hrow = (float4*)(h + (size_t)v * HDIM);
        hrow[lane]      = a0;
        hrow[lane + 32] = a1;
        ssum[0] += a0.x; ssum[1] += a0.y; ssum[2] += a0.z; ssum[3] += a0.w;
        ssum[4] += a1.x; ssum[5] += a1.y; ssum[6] += a1.z; ssum[7] += a1.w;
        ssq[0] += a0.x * a0.x; ssq[1] += a0.y * a0.y;
        ssq[2] += a0.z * a0.z; ssq[3] += a0.w * a0.w;
        ssq[4] += a1.x * a1.x; ssq[5] += a1.y * a1.y;
        ssq[6] += a1.z * a1.z; ssq[7] += a1.w * a1.w;
    }
    __syncthreads();
#pragma unroll
    for (int k = 0; k < 4; k++) {
        atomicAdd(&s_sum[lane * 4 + k], ssum[k]);
        atomicAdd(&s_sum[128 + lane * 4 + k], ssum[4 + k]);
        atomicAdd(&s_sq[lane * 4 + k], ssq[k]);
        atomicAdd(&s_sq[128 + lane * 4 + k], ssq[4 + k]);
    }
    __syncthreads();
    atomicAdd(&gsum[tid], s_sum[tid]);
    atomicAdd(&gsq[tid], s_sq[tid]);
}

// ---------------- BN helpers ------------------------------------------------
__global__ void zero_stats_kernel(float* sum, float* sumsq) {
    int t = threadIdx.x;
    sum[t] = 0.f;
    sumsq[t] = 0.f;
}

__global__ void bn_apply_kernel(float* __restrict__ h,
                                float* __restrict__ acc,
                                const float* __restrict__ sum,
                                const float* __restrict__ sumsq,
                                const float* __restrict__ gamma,
                                const float* __restrict__ beta,
                                const float* __restrict__ w, int layer) {
    int idx = blockIdx.x * blockDim.x + threadIdx.x;
    if (idx >= N_NODES * HDIM) return;
    int f = idx & 255;
    const float invN = 1.0f / (float)N_NODES;
    float mu  = sum[f] * invN;
    float var = sumsq[f] * invN - mu * mu;
    float v = (h[idx] - mu) * rsqrtf(var + BN_EPS) * gamma[f] + beta[f];
    v = fmaxf(v, 0.f);
    h[idx] = v;
    acc[idx] += w[layer] * v;
}

__global__ void zero_acc_kernel(float* acc) {
    int idx = blockIdx.x * blockDim.x + threadIdx.x;
    if (idx < N_NODES * HDIM) acc[idx] = 0.f;
}

// ---------------- log-softmax -----------------------------------------------
__global__ void logsoftmax_kernel(const float* __restrict__ logits,
                                  float* __restrict__ out) {
    int row  = blockIdx.x * 8 + (threadIdx.x >> 5);
    int lane = threadIdx.x & 31;
    if (row >= N_NODES) return;
    const float* lr = logits + (size_t)row * C_OUT;

    float vals[4];
    int cnt = 0;
    float m = -1e30f;
    for (int f = lane; f < C_OUT; f += 32) {
        vals[cnt] = lr[f];
        m = fmaxf(m, vals[cnt]);
        cnt++;
    }
#pragma unroll
    for (int off = 16; off >= 1; off >>= 1)
        m = fmaxf(m, __shfl_xor_sync(0xffffffffu, m, off));
    float s = 0.f;
    for (int i = 0; i < cnt; i++) s += expf(vals[i] - m);
#pragma unroll
    for (int off = 16; off >= 1; off >>= 1)
        s += __shfl_xor_sync(0xffffffffu, s, off);
    float lse = m + logf(s);
    cnt = 0;
    for (int f = lane; f < C_OUT; f += 32) {
        out[(size_t)row * C_OUT + f] = vals[cnt] - lse;
        cnt++;
    }
}

// ---------------- host launcher ---------------------------------------------
extern "C" void kernel_launch(void* const* d_in, const int* in_sizes, int n_in,
                              void* d_out, int out_size) {
    const float* x       = (const float*)d_in[0];
    const int*   e1      = (const int*)  d_in[1];
    const int*   e2      = (const int*)  d_in[2];
    const float* in_W    = (const float*)d_in[3];
    const float* in_b    = (const float*)d_in[4];
    const float* convW   = (const float*)d_in[5];
    const float* convB   = (const float*)d_in[6];
    const float* bng     = (const float*)d_in[7];
    const float* bnb     = (const float*)d_in[8];
    const float* out_W   = (const float*)d_in[9];
    const float* out_b   = (const float*)d_in[10];
    const float* layer_w = (const float*)d_in[11];
    float* out = (float*)d_out;

    float *p_h, *p_t, *p_acc, *p_logits, *p_dinv1, *p_dinv2, *p_sum, *p_sumsq, *p_w;
    int *p_cnt, *p_rp1, *p_rp2, *p_cur, *p_csr1, *p_csr2;
    cudaGetSymbolAddress((void**)&p_h, g_h);
    cudaGetSymbolAddress((void**)&p_t, g_t);
    cudaGetSymbolAddress((void**)&p_acc, g_acc);
    cudaGetSymbolAddress((void**)&p_logits, g_logits);
    cudaGetSymbolAddress((void**)&p_dinv1, g_dinv1);
    cudaGetSymbolAddress((void**)&p_dinv2, g_dinv2);
    cudaGetSymbolAddress((void**)&p_sum, g_sum);
    cudaGetSymbolAddress((void**)&p_sumsq, g_sumsq);
    cudaGetSymbolAddress((void**)&p_w, g_w);
    cudaGetSymbolAddress((void**)&p_cnt, g_cnt);
    cudaGetSymbolAddress((void**)&p_rp1, g_rp1);
    cudaGetSymbolAddress((void**)&p_rp2, g_rp2);
    cudaGetSymbolAddress((void**)&p_cur, g_cur);
    cudaGetSymbolAddress((void**)&p_csr1, g_csr1);
    cudaGetSymbolAddress((void**)&p_csr2, g_csr2);

    const int nThr = 256;
    const int nbN  = (N_NODES + nThr - 1) / nThr;
    const int nbE  = (E_EDGES + nThr - 1) / nThr;
    const int nbNH = (N_NODES * HDIM + nThr - 1) / nThr;
    const dim3 gemmH(HDIM / BN, (N_NODES + BM - 1) / BM);
    const dim3 gemmC(1, (N_NODES + BM - 1) / BM);
    const int aggBlocks = 1480;  // 8 warps each, grid-stride over nodes

    // ---- build CSR + dinv for both adjacencies ----
    {
        zero_cnt_kernel<<<nbN, nThr>>>(p_cnt);
        hist_kernel<<<nbE, nThr>>>(e1 + E_EDGES, p_cnt);
        scan_kernel<<<1, 1024>>>(p_cnt, p_rp1);
        dinv_from_rp_kernel<<<nbN, nThr>>>(p_rp1, p_dinv1);
        cursor_copy_kernel<<<nbN, nThr>>>(p_rp1, p_cur);
        fill_kernel<<<nbE, nThr>>>(e1, e1 + E_EDGES, p_cur, p_csr1);

        zero_cnt_kernel<<<nbN, nThr>>>(p_cnt);
        hist_kernel<<<nbE, nThr>>>(e2 + E_EDGES, p_cnt);
        scan_kernel<<<1, 1024>>>(p_cnt, p_rp2);
        dinv_from_rp_kernel<<<nbN, nThr>>>(p_rp2, p_dinv2);
        cursor_copy_kernel<<<nbN, nThr>>>(p_rp2, p_cur);
        fill_kernel<<<nbE, nThr>>>(e2, e2 + E_EDGES, p_cur, p_csr2);
    }

    softmax_w_kernel<<<1, 1>>>(layer_w, p_w);
    zero_acc_kernel<<<nbNH, nThr>>>(p_acc);

    // input FC
    gemm_bias_kernel<<<gemmH, nThr>>>(x, in_W, in_b, nullptr, p_h,
                                      N_NODES, HDIM, F_INPUT);

    for (int l = 0; l < L_LAYERS; l++) {
        const int*   rp   = (l < L_LAYERS / 2) ? p_rp1 : p_rp2;
        const int*   csr  = (l < L_LAYERS / 2) ? p_csr1 : p_csr2;
        const float* dinv = (l < L_LAYERS / 2) ? p_dinv1 : p_dinv2;

        // t' = (h @ convW[l] + convB[l]) * dinv[row]
        gemm_bias_kernel<<<gemmH, nThr>>>(p_h, convW + (size_t)l * HDIM * HDIM,
                                          convB + l * HDIM, dinv, p_t,
                                          N_NODES, HDIM, HDIM);
        // h = dinv * (t'_self + sum of in-neighbors), fused BN stats
        zero_stats_kernel<<<1, HDIM>>>(p_sum, p_sumsq);
        agg_kernel<<<aggBlocks, nThr>>>(rp, csr, dinv, p_t, p_h, p_sum, p_sumsq);
        // BN apply + ReLU + weighted residual
        bn_apply_kernel<<<nbNH, nThr>>>(p_h, p_acc, p_sum, p_sumsq,
                                        bng + l * HDIM, bnb + l * HDIM, p_w, l);
    }

    gemm_bias_kernel<<<gemmC, nThr>>>(p_acc, out_W, out_b, nullptr, p_logits,
                                      N_NODES, C_OUT, HDIM);
    logsoftmax_kernel<<<(N_NODES + 7) / 8, nThr>>>(p_logits, out);
}

// round 5
// speedup vs baseline: 3.5730x; 1.1085x over previous
#include <cuda_runtime.h>
#include <cuda_bf16.h>
#include <math.h>
#include <stdint.h>

#define N_NODES 50000
#define E_EDGES 800000
#define F_INPUT 128
#define HDIM    256
#define C_OUT   112
#define L_LAYERS 8
#define BN_EPS  1e-5f

// ---------------- scratch (device globals; no allocations anywhere) --------
__device__ float g_h[N_NODES * HDIM];
__device__ float g_t[N_NODES * HDIM];
__device__ float g_acc[N_NODES * HDIM];
__device__ float g_logits[N_NODES * C_OUT];
__device__ __nv_bfloat16 g_hbh[N_NODES * HDIM];
__device__ __nv_bfloat16 g_hbl[N_NODES * HDIM];
__device__ __nv_bfloat16 g_wth[L_LAYERS * HDIM * HDIM];  // W^T hi [l][n][k]
__device__ __nv_bfloat16 g_wtl[L_LAYERS * HDIM * HDIM];  // W^T lo
__device__ float g_dinv1[N_NODES];
__device__ float g_dinv2[N_NODES];
__device__ float g_sum[HDIM];
__device__ float g_sumsq[HDIM];
__device__ float g_w[L_LAYERS];
__device__ int g_cnt[N_NODES];
__device__ int g_rp1[N_NODES + 1];
__device__ int g_rp2[N_NODES + 1];
__device__ int g_cur[N_NODES];
__device__ int g_csr1[E_EDGES];
__device__ int g_csr2[E_EDGES];

// ---------------- helpers ---------------------------------------------------
__device__ __forceinline__ uint32_t smem_u32(const void* p) {
    uint32_t a;
    asm("{ .reg .u64 t; cvta.to.shared.u64 t, %1; cvt.u32.u64 %0, t; }"
        : "=r"(a) : "l"(p));
    return a;
}
__device__ __forceinline__ unsigned long long pk2(float lo, float hi) {
    unsigned long long r;
    asm("mov.b64 %0, {%1, %2};" : "=l"(r) : "f"(lo), "f"(hi));
    return r;
}
__device__ __forceinline__ void upk2(float& lo, float& hi, unsigned long long v) {
    asm("mov.b64 {%0, %1}, %2;" : "=f"(lo), "=f"(hi) : "l"(v));
}
__device__ __forceinline__ void ffma2(unsigned long long& d,
                                      unsigned long long a, unsigned long long b) {
    asm("fma.rn.f32x2 %0, %1, %2, %0;" : "+l"(d) : "l"(a), "l"(b));
}
__device__ __forceinline__ void ldm_x4(uint32_t& r0, uint32_t& r1,
                                       uint32_t& r2, uint32_t& r3, uint32_t addr) {
    asm volatile("ldmatrix.sync.aligned.m8n8.x4.shared.b16 {%0,%1,%2,%3}, [%4];"
                 : "=r"(r0), "=r"(r1), "=r"(r2), "=r"(r3) : "r"(addr));
}
__device__ __forceinline__ void mma_bf16(float* d, const uint32_t* a,
                                         uint32_t b0, uint32_t b1) {
    asm volatile(
        "mma.sync.aligned.m16n8k16.row.col.f32.bf16.bf16.f32 "
        "{%0,%1,%2,%3}, {%4,%5,%6,%7}, {%8,%9}, {%0,%1,%2,%3};"
        : "+f"(d[0]), "+f"(d[1]), "+f"(d[2]), "+f"(d[3])
        : "r"(a[0]), "r"(a[1]), "r"(a[2]), "r"(a[3]), "r"(b0), "r"(b1));
}

// ---------------- weight transpose + bf16 split ----------------------------
__global__ void weight_prep_kernel(const float* __restrict__ convW,
                                   __nv_bfloat16* wth, __nv_bfloat16* wtl) {
    int i = blockIdx.x * blockDim.x + threadIdx.x;
    if (i >= L_LAYERS * HDIM * HDIM) return;
    int l = i >> 16;
    int n = (i >> 8) & 255;
    int k = i & 255;
    float v = convW[(l << 16) + (k << 8) + n];
    __nv_bfloat16 hi = __float2bfloat16(v);
    wth[i] = hi;
    wtl[i] = __float2bfloat16(v - __bfloat162float(hi));
}

__global__ void split_kernel(const float* __restrict__ h,
                             __nv_bfloat16* hbh, __nv_bfloat16* hbl) {
    int i = blockIdx.x * blockDim.x + threadIdx.x;
    if (i >= N_NODES * HDIM) return;
    float v = h[i];
    __nv_bfloat16 hi = __float2bfloat16(v);
    hbh[i] = hi;
    hbl[i] = __float2bfloat16(v - __bfloat162float(hi));
}

// ---------------- CSR build -------------------------------------------------
__global__ void zero_cnt_kernel(int* cnt) {
    int i = blockIdx.x * blockDim.x + threadIdx.x;
    if (i < N_NODES) cnt[i] = 0;
}
__global__ void hist_kernel(const int* __restrict__ tgt, int* cnt) {
    int i = blockIdx.x * blockDim.x + threadIdx.x;
    if (i < E_EDGES) atomicAdd(&cnt[tgt[i]], 1);
}
__global__ void scan_kernel(const int* __restrict__ cnt, int* rowptr) {
    __shared__ int s[1024];
    const int T = 1024;
    const int CH = (N_NODES + T - 1) / T;
    int t = threadIdx.x;
    int base = t * CH;
    int loc = 0;
    for (int i = 0; i < CH; i++) {
        int idx = base + i;
        if (idx < N_NODES) loc += cnt[idx];
    }
    s[t] = loc;
    __syncthreads();
    for (int off = 1; off < T; off <<= 1) {
        int v = (t >= off) ? s[t - off] : 0;
        __syncthreads();
        s[t] += v;
        __syncthreads();
    }
    int run = s[t] - loc;
    for (int i = 0; i < CH; i++) {
        int idx = base + i;
        if (idx < N_NODES) {
            rowptr[idx] = run;
            run += cnt[idx];
        }
    }
    if (t == T - 1) rowptr[N_NODES] = run;
}
__global__ void dinv_from_rp_kernel(const int* __restrict__ rowptr, float* dinv) {
    int i = blockIdx.x * blockDim.x + threadIdx.x;
    if (i < N_NODES)
        dinv[i] = rsqrtf((float)(rowptr[i + 1] - rowptr[i]) + 1.0f);
}
__global__ void cursor_copy_kernel(const int* __restrict__ rowptr, int* cur) {
    int i = blockIdx.x * blockDim.x + threadIdx.x;
    if (i < N_NODES) cur[i] = rowptr[i];
}
__global__ void fill_kernel(const int* __restrict__ src, const int* __restrict__ tgt,
                            int* cur, int* csr) {
    int i = blockIdx.x * blockDim.x + threadIdx.x;
    if (i < E_EDGES) {
        int pos = atomicAdd(&cur[tgt[i]], 1);
        csr[pos] = src[i];
    }
}

__global__ void softmax_w_kernel(const float* __restrict__ lw, float* w) {
    float m = -1e30f;
    for (int i = 0; i < L_LAYERS; i++) m = fmaxf(m, lw[i]);
    float s = 0.f;
    for (int i = 0; i < L_LAYERS; i++) s += expf(lw[i] - m);
    for (int i = 0; i < L_LAYERS; i++) w[i] = expf(lw[i] - m) / s;
}

// ---------------- SIMT FFMA2 GEMM (in/out FC) ------------------------------
#define BM 128
#define BN 128
#define BK 16
__global__ __launch_bounds__(256, 2)
void gemm_bias_kernel(const float* __restrict__ A, const float* __restrict__ B,
                      const float* __restrict__ bias, const float* __restrict__ dinv,
                      float* __restrict__ C, int M, int Nc, int K) {
    __shared__ float As[2][BK][BM + 4];
    __shared__ float Bs[2][BK][BN];
    const int tid  = threadIdx.x;
    const int tRow = tid >> 4;
    const int tCol = tid & 15;
    const int brow = blockIdx.y * BM;
    const int bcol = blockIdx.x * BN;
    const int am0 = tid >> 2;
    const int am1 = (tid + 256) >> 2;
    const int ak  = (tid & 3) * 4;
    const int arow0 = min(brow + am0, M - 1);
    const int arow1 = min(brow + am1, M - 1);
    const int bk0 = tid >> 5;
    const int bk1 = bk0 + 8;
    const int bnx = (tid & 31) * 4;
    const bool bok = (bcol + bnx + 3) < Nc;
    const int bcl  = bok ? (bcol + bnx) : 0;

    unsigned long long acc[8][4];
#pragma unroll
    for (int i = 0; i < 8; i++)
#pragma unroll
        for (int j = 0; j < 4; j++) acc[i][j] = 0ull;

    float4 aR0, aR1, bR0, bR1;
    const float4 z4 = make_float4(0.f, 0.f, 0.f, 0.f);
    aR0 = *(const float4*)(A + (size_t)arow0 * K + ak);
    aR1 = *(const float4*)(A + (size_t)arow1 * K + ak);
    bR0 = bok ? *(const float4*)(B + (size_t)bk0 * Nc + bcl) : z4;
    bR1 = bok ? *(const float4*)(B + (size_t)bk1 * Nc + bcl) : z4;
    As[0][ak + 0][am0] = aR0.x; As[0][ak + 1][am0] = aR0.y;
    As[0][ak + 2][am0] = aR0.z; As[0][ak + 3][am0] = aR0.w;
    As[0][ak + 0][am1] = aR1.x; As[0][ak + 1][am1] = aR1.y;
    As[0][ak + 2][am1] = aR1.z; As[0][ak + 3][am1] = aR1.w;
    *(float4*)&Bs[0][bk0][bnx] = bR0;
    *(float4*)&Bs[0][bk1][bnx] = bR1;
    __syncthreads();

    const int nt = K / BK;
    for (int kt = 0; kt < nt; kt++) {
        const int buf = kt & 1;
        const int nxt = kt + 1;
        if (nxt < nt) {
            const int k0 = nxt * BK;
            aR0 = *(const float4*)(A + (size_t)arow0 * K + k0 + ak);
            aR1 = *(const float4*)(A + (size_t)arow1 * K + k0 + ak);
            bR0 = bok ? *(const float4*)(B + (size_t)(k0 + bk0) * Nc + bcl) : z4;
            bR1 = bok ? *(const float4*)(B + (size_t)(k0 + bk1) * Nc + bcl) : z4;
        }
#pragma unroll
        for (int k = 0; k < BK; k++) {
            float4 a0 = *(const float4*)&As[buf][k][tRow * 4];
            float4 a1 = *(const float4*)&As[buf][k][64 + tRow * 4];
            float4 b0 = *(const float4*)&Bs[buf][k][tCol * 4];
            float4 b1 = *(const float4*)&Bs[buf][k][64 + tCol * 4];
            unsigned long long bb[4] = {pk2(b0.x, b0.y), pk2(b0.z, b0.w),
                                        pk2(b1.x, b1.y), pk2(b1.z, b1.w)};
            float av[8] = {a0.x, a0.y, a0.z, a0.w, a1.x, a1.y, a1.z, a1.w};
#pragma unroll
            for (int i = 0; i < 8; i++) {
                unsigned long long ap = pk2(av[i], av[i]);
#pragma unroll
                for (int j = 0; j < 4; j++) ffma2(acc[i][j], ap, bb[j]);
            }
        }
        if (nxt < nt) {
            const int nb = nxt & 1;
            As[nb][ak + 0][am0] = aR0.x; As[nb][ak + 1][am0] = aR0.y;
            As[nb][ak + 2][am0] = aR0.z; As[nb][ak + 3][am0] = aR0.w;
            As[nb][ak + 0][am1] = aR1.x; As[nb][ak + 1][am1] = aR1.y;
            As[nb][ak + 2][am1] = aR1.z; As[nb][ak + 3][am1] = aR1.w;
            *(float4*)&Bs[nb][bk0][bnx] = bR0;
            *(float4*)&Bs[nb][bk1][bnx] = bR1;
        }
        __syncthreads();
    }

#pragma unroll
    for (int ih = 0; ih < 2; ih++) {
#pragma unroll
        for (int i = 0; i < 4; i++) {
            int r = brow + ih * 64 + tRow * 4 + i;
            if (r >= M) continue;
            float ds = dinv ? dinv[r] : 1.0f;
#pragma unroll
            for (int jh = 0; jh < 2; jh++) {
                int c = bcol + jh * 64 + tCol * 4;
                if (c + 3 < Nc) {
                    float4 o;
                    float e0, e1, e2, e3;
                    upk2(e0, e1, acc[ih * 4 + i][jh * 2 + 0]);
                    upk2(e2, e3, acc[ih * 4 + i][jh * 2 + 1]);
                    o.x = (e0 + bias[c + 0]) * ds;
                    o.y = (e1 + bias[c + 1]) * ds;
                    o.z = (e2 + bias[c + 2]) * ds;
                    o.w = (e3 + bias[c + 3]) * ds;
                    *(float4*)(C + (size_t)r * Nc + c) = o;
                }
            }
        }
    }
}

// ---------------- mma.sync bf16-split GEMM (conv layers) -------------------
// C[M,256] = (Ahi+Alo) @ (Bhi+Blo)^T, B stored [256][256] K-major (W^T).
// CTA tile 128x128, warp tile 32x64, K chunk 32. Rows padded to 40 bf16 (80B)
// -> ldmatrix banks (20r+4u)%32 all distinct, conflict-free.
#define SROW 40

__global__ __launch_bounds__(256)
void mma_gemm_kernel(const __nv_bfloat16* __restrict__ Ah,
                     const __nv_bfloat16* __restrict__ Al,
                     const __nv_bfloat16* __restrict__ Bh,
                     const __nv_bfloat16* __restrict__ Bl,
                     const float* __restrict__ bias,
                     const float* __restrict__ dinv,
                     float* __restrict__ C, int M) {
    __shared__ __nv_bfloat16 sAh[128 * SROW];
    __shared__ __nv_bfloat16 sAl[128 * SROW];
    __shared__ __nv_bfloat16 sBh[128 * SROW];
    __shared__ __nv_bfloat16 sBl[128 * SROW];

    const int tid  = threadIdx.x;
    const int lane = tid & 31;
    const int wid  = tid >> 5;
    const int wm   = wid & 3;      // 0..3 -> m offset 32*wm
    const int wn   = wid >> 2;     // 0..1 -> n offset 64*wn
    const int brow = blockIdx.y * 128;
    const int bcol = blockIdx.x * 128;

    // staging: idx -> row=idx/4, unit=idx%4 (8 bf16 per unit)
    const int rA  = tid >> 2;       // 0..63
    const int un  = tid & 3;
    const int gr0 = min(brow + rA, M - 1);
    const int gr1 = min(brow + rA + 64, M - 1);
    const int bn0 = bcol + rA;       // weight rows always < 256
    const int bn1 = bcol + rA + 64;
    const uint32_t st0 = (uint32_t)(rA * SROW + un * 8) * 2;        // bytes
    const uint32_t st1 = st0 + 64 * SROW * 2;

    const uint32_t sbAh = smem_u32(sAh);
    const uint32_t sbAl = smem_u32(sAl);
    const uint32_t sbBh = smem_u32(sBh);
    const uint32_t sbBl = smem_u32(sBl);

    // ldmatrix lane offsets
    const int li = lane & 7;
    const int lb = (lane >> 3) & 1;
    const int lc = (lane >> 4) & 1;
    uint32_t aoff[2], boff[4];
#pragma unroll
    for (int mf = 0; mf < 2; mf++)
        aoff[mf] = (uint32_t)((wm * 32 + mf * 16 + lb * 8 + li) * SROW + lc * 8) * 2;
#pragma unroll
    for (int nf = 0; nf < 4; nf++)
        boff[nf] = (uint32_t)((wn * 64 + nf * 16 + lc * 8 + li) * SROW + lb * 8) * 2;

    float acc[2][8][4];
#pragma unroll
    for (int i = 0; i < 2; i++)
#pragma unroll
        for (int j = 0; j < 8; j++)
#pragma unroll
            for (int k = 0; k < 4; k++) acc[i][j][k] = 0.f;

    for (int c = 0; c < 8; c++) {
        const int kb = c * 32;
        float4 vA0 = *(const float4*)(Ah + (size_t)gr0 * HDIM + kb + un * 8);
        float4 vA1 = *(const float4*)(Ah + (size_t)gr1 * HDIM + kb + un * 8);
        float4 vL0 = *(const float4*)(Al + (size_t)gr0 * HDIM + kb + un * 8);
        float4 vL1 = *(const float4*)(Al + (size_t)gr1 * HDIM + kb + un * 8);
        float4 wH0 = *(const float4*)(Bh + (size_t)bn0 * HDIM + kb + un * 8);
        float4 wH1 = *(const float4*)(Bh + (size_t)bn1 * HDIM + kb + un * 8);
        float4 wL0 = *(const float4*)(Bl + (size_t)bn0 * HDIM + kb + un * 8);
        float4 wL1 = *(const float4*)(Bl + (size_t)bn1 * HDIM + kb + un * 8);
        __syncthreads();   // prior chunk's ldmatrix reads done
        *(float4*)((char*)sAh + st0) = vA0;
        *(float4*)((char*)sAh + st1) = vA1;
        *(float4*)((char*)sAl + st0) = vL0;
        *(float4*)((char*)sAl + st1) = vL1;
        *(float4*)((char*)sBh + st0) = wH0;
        *(float4*)((char*)sBh + st1) = wH1;
        *(float4*)((char*)sBl + st0) = wL0;
        *(float4*)((char*)sBl + st1) = wL1;
        __syncthreads();

#pragma unroll
        for (int ks = 0; ks < 2; ks++) {
            const uint32_t kadd = ks * 32;   // 16 bf16 = 32 bytes
            uint32_t A0h[4], A1h[4], A0l[4], A1l[4];
            ldm_x4(A0h[0], A0h[1], A0h[2], A0h[3], sbAh + aoff[0] + kadd);
            ldm_x4(A1h[0], A1h[1], A1h[2], A1h[3], sbAh + aoff[1] + kadd);
            ldm_x4(A0l[0], A0l[1], A0l[2], A0l[3], sbAl + aoff[0] + kadd);
            ldm_x4(A1l[0], A1l[1], A1l[2], A1l[3], sbAl + aoff[1] + kadd);
#pragma unroll
            for (int nf = 0; nf < 4; nf++) {
                uint32_t bh[4], bl[4];
                ldm_x4(bh[0], bh[1], bh[2], bh[3], sbBh + boff[nf] + kadd);
                ldm_x4(bl[0], bl[1], bl[2], bl[3], sbBl + boff[nf] + kadd);
                // n-frag nf*2 : b = {r0,r1};  nf*2+1 : b = {r2,r3}
                mma_bf16(acc[0][nf * 2 + 0], A0h, bh[0], bh[1]);
                mma_bf16(acc[0][nf * 2 + 0], A0h, bl[0], bl[1]);
                mma_bf16(acc[0][nf * 2 + 0], A0l, bh[0], bh[1]);
                mma_bf16(acc[0][nf * 2 + 1], A0h, bh[2], bh[3]);
                mma_bf16(acc[0][nf * 2 + 1], A0h, bl[2], bl[3]);
                mma_bf16(acc[0][nf * 2 + 1], A0l, bh[2], bh[3]);
                mma_bf16(acc[1][nf * 2 + 0], A1h, bh[0], bh[1]);
                mma_bf16(acc[1][nf * 2 + 0], A1h, bl[0], bl[1]);
                mma_bf16(acc[1][nf * 2 + 0], A1l, bh[0], bh[1]);
                mma_bf16(acc[1][nf * 2 + 1], A1h, bh[2], bh[3]);
                mma_bf16(acc[1][nf * 2 + 1], A1h, bl[2], bl[3]);
                mma_bf16(acc[1][nf * 2 + 1], A1l, bh[2], bh[3]);
            }
        }
    }

    // epilogue: C[r, c] = (acc + bias[c]) * dinv[r]
    const int qr = lane >> 2;
    const int qc = (lane & 3) * 2;
#pragma unroll
    for (int mf = 0; mf < 2; mf++) {
        int r0 = brow + wm * 32 + mf * 16 + qr;
        int r1 = r0 + 8;
        float dv0 = (r0 < M) ? dinv[r0] : 0.f;
        float dv1 = (r1 < M) ? dinv[r1] : 0.f;
#pragma unroll
        for (int nf = 0; nf < 8; nf++) {
            int cc = bcol + wn * 64 + nf * 8 + qc;
            float b0 = bias[cc], b1 = bias[cc + 1];
            if (r0 < M) {
                float2 o = make_float2((acc[mf][nf][0] + b0) * dv0,
                                       (acc[mf][nf][1] + b1) * dv0);
                *(float2*)(C + (size_t)r0 * HDIM + cc) = o;
            }
            if (r1 < M) {
                float2 o = make_float2((acc[mf][nf][2] + b0) * dv1,
                                       (acc[mf][nf][3] + b1) * dv1);
                *(float2*)(C + (size_t)r1 * HDIM + cc) = o;
            }
        }
    }
}

// ---------------- CSR aggregation + fused BN stats --------------------------
__global__ __launch_bounds__(256)
void agg_kernel(const int* __restrict__ rowptr, const int* __restrict__ csr,
                const float* __restrict__ dinv, const float* __restrict__ tp,
                float* __restrict__ h, float* gsum, float* gsq) {
    __shared__ float s_sum[HDIM];
    __shared__ float s_sq[HDIM];
    int tid  = threadIdx.x;
    int lane = tid & 31;
    int warp = tid >> 5;
    int gw   = blockIdx.x * 8 + warp;
    int nw   = gridDim.x * 8;

    s_sum[tid] = 0.f;
    s_sq[tid]  = 0.f;

    float ssum[8], ssq[8];
#pragma unroll
    for (int i = 0; i < 8; i++) { ssum[i] = 0.f; ssq[i] = 0.f; }

    for (int v = gw; v < N_NODES; v += nw) {
        const float4* self = (const float4*)(tp + (size_t)v * HDIM);
        float4 a0 = self[lane];
        float4 a1 = self[lane + 32];
        int beg = rowptr[v], end = rowptr[v + 1];
        int e = beg;
        for (; e + 1 < end; e += 2) {
            int s0 = csr[e], s1 = csr[e + 1];
            const float4* r0 = (const float4*)(tp + (size_t)s0 * HDIM);
            const float4* r1 = (const float4*)(tp + (size_t)s1 * HDIM);
            float4 v00 = r0[lane], v01 = r0[lane + 32];
            float4 v10 = r1[lane], v11 = r1[lane + 32];
            a0.x += v00.x + v10.x; a0.y += v00.y + v10.y;
            a0.z += v00.z + v10.z; a0.w += v00.w + v10.w;
            a1.x += v01.x + v11.x; a1.y += v01.y + v11.y;
            a1.z += v01.z + v11.z; a1.w += v01.w + v11.w;
        }
        if (e < end) {
            int s0 = csr[e];
            const float4* r0 = (const float4*)(tp + (size_t)s0 * HDIM);
            float4 v00 = r0[lane], v01 = r0[lane + 32];
            a0.x += v00.x; a0.y += v00.y; a0.z += v00.z; a0.w += v00.w;
            a1.x += v01.x; a1.y += v01.y; a1.z += v01.z; a1.w += v01.w;
        }
        float dv = dinv[v];
        a0.x *= dv; a0.y *= dv; a0.z *= dv; a0.w *= dv;
        a1.x *= dv; a1.y *= dv; a1.z *= dv; a1.w *= dv;
        float4* hrow = (float4*)(h + (size_t)v * HDIM);
        hrow[lane]      = a0;
        hrow[lane + 32] = a1;
        ssum[0] += a0.x; ssum[1] += a0.y; ssum[2] += a0.z; ssum[3] += a0.w;
        ssum[4] += a1.x; ssum[5] += a1.y; ssum[6] += a1.z; ssum[7] += a1.w;
        ssq[0] += a0.x * a0.x; ssq[1] += a0.y * a0.y;
        ssq[2] += a0.z * a0.z; ssq[3] += a0.w * a0.w;
        ssq[4] += a1.x * a1.x; ssq[5] += a1.y * a1.y;
        ssq[6] += a1.z * a1.z; ssq[7] += a1.w * a1.w;
    }
    __syncthreads();
#pragma unroll
    for (int k = 0; k < 4; k++) {
        atomicAdd(&s_sum[lane * 4 + k], ssum[k]);
        atomicAdd(&s_sum[128 + lane * 4 + k], ssum[4 + k]);
        atomicAdd(&s_sq[lane * 4 + k], ssq[k]);
        atomicAdd(&s_sq[128 + lane * 4 + k], ssq[4 + k]);
    }
    __syncthreads();
    atomicAdd(&gsum[tid], s_sum[tid]);
    atomicAdd(&gsq[tid], s_sq[tid]);
}

// ---------------- BN helpers ------------------------------------------------
__global__ void zero_stats_kernel(float* sum, float* sumsq) {
    int t = threadIdx.x;
    sum[t] = 0.f;
    sumsq[t] = 0.f;
}

__global__ void bn_apply_kernel(const float* __restrict__ h,
                                float* __restrict__ acc,
                                __nv_bfloat16* __restrict__ hbh,
                                __nv_bfloat16* __restrict__ hbl,
                                const float* __restrict__ sum,
                                const float* __restrict__ sumsq,
                                const float* __restrict__ gamma,
                                const float* __restrict__ beta,
                                const float* __restrict__ w, int layer) {
    int idx = blockIdx.x * blockDim.x + threadIdx.x;
    if (idx >= N_NODES * HDIM) return;
    int f = idx & 255;
    const float invN = 1.0f / (float)N_NODES;
    float mu  = sum[f] * invN;
    float var = sumsq[f] * invN - mu * mu;
    float v = (h[idx] - mu) * rsqrtf(var + BN_EPS) * gamma[f] + beta[f];
    v = fmaxf(v, 0.f);
    __nv_bfloat16 hi = __float2bfloat16(v);
    hbh[idx] = hi;
    hbl[idx] = __float2bfloat16(v - __bfloat162float(hi));
    acc[idx] += w[layer] * v;
}

__global__ void zero_acc_kernel(float* acc) {
    int idx = blockIdx.x * blockDim.x + threadIdx.x;
    if (idx < N_NODES * HDIM) acc[idx] = 0.f;
}

// ---------------- log-softmax -----------------------------------------------
__global__ void logsoftmax_kernel(const float* __restrict__ logits,
                                  float* __restrict__ out) {
    int row  = blockIdx.x * 8 + (threadIdx.x >> 5);
    int lane = threadIdx.x & 31;
    if (row >= N_NODES) return;
    const float* lr = logits + (size_t)row * C_OUT;
    float vals[4];
    int cnt = 0;
    float m = -1e30f;
    for (int f = lane; f < C_OUT; f += 32) {
        vals[cnt] = lr[f];
        m = fmaxf(m, vals[cnt]);
        cnt++;
    }
#pragma unroll
    for (int off = 16; off >= 1; off >>= 1)
        m = fmaxf(m, __shfl_xor_sync(0xffffffffu, m, off));
    float s = 0.f;
    for (int i = 0; i < cnt; i++) s += expf(vals[i] - m);
#pragma unroll
    for (int off = 16; off >= 1; off >>= 1)
        s += __shfl_xor_sync(0xffffffffu, s, off);
    float lse = m + logf(s);
    cnt = 0;
    for (int f = lane; f < C_OUT; f += 32) {
        out[(size_t)row * C_OUT + f] = vals[cnt] - lse;
        cnt++;
    }
}

// ---------------- host launcher ---------------------------------------------
extern "C" void kernel_launch(void* const* d_in, const int* in_sizes, int n_in,
                              void* d_out, int out_size) {
    const float* x       = (const float*)d_in[0];
    const int*   e1      = (const int*)  d_in[1];
    const int*   e2      = (const int*)  d_in[2];
    const float* in_W    = (const float*)d_in[3];
    const float* in_b    = (const float*)d_in[4];
    const float* convW   = (const float*)d_in[5];
    const float* convB   = (const float*)d_in[6];
    const float* bng     = (const float*)d_in[7];
    const float* bnb     = (const float*)d_in[8];
    const float* out_W   = (const float*)d_in[9];
    const float* out_b   = (const float*)d_in[10];
    const float* layer_w = (const float*)d_in[11];
    float* out = (float*)d_out;

    float *p_h, *p_t, *p_acc, *p_logits, *p_dinv1, *p_dinv2, *p_sum, *p_sumsq, *p_w;
    __nv_bfloat16 *p_hbh, *p_hbl, *p_wth, *p_wtl;
    int *p_cnt, *p_rp1, *p_rp2, *p_cur, *p_csr1, *p_csr2;
    cudaGetSymbolAddress((void**)&p_h, g_h);
    cudaGetSymbolAddress((void**)&p_t, g_t);
    cudaGetSymbolAddress((void**)&p_acc, g_acc);
    cudaGetSymbolAddress((void**)&p_logits, g_logits);
    cudaGetSymbolAddress((void**)&p_hbh, g_hbh);
    cudaGetSymbolAddress((void**)&p_hbl, g_hbl);
    cudaGetSymbolAddress((void**)&p_wth, g_wth);
    cudaGetSymbolAddress((void**)&p_wtl, g_wtl);
    cudaGetSymbolAddress((void**)&p_dinv1, g_dinv1);
    cudaGetSymbolAddress((void**)&p_dinv2, g_dinv2);
    cudaGetSymbolAddress((void**)&p_sum, g_sum);
    cudaGetSymbolAddress((void**)&p_sumsq, g_sumsq);
    cudaGetSymbolAddress((void**)&p_w, g_w);
    cudaGetSymbolAddress((void**)&p_cnt, g_cnt);
    cudaGetSymbolAddress((void**)&p_rp1, g_rp1);
    cudaGetSymbolAddress((void**)&p_rp2, g_rp2);
    cudaGetSymbolAddress((void**)&p_cur, g_cur);
    cudaGetSymbolAddress((void**)&p_csr1, g_csr1);
    cudaGetSymbolAddress((void**)&p_csr2, g_csr2);

    const int nThr = 256;
    const int nbN  = (N_NODES + nThr - 1) / nThr;
    const int nbE  = (E_EDGES + nThr - 1) / nThr;
    const int nbNH = (N_NODES * HDIM + nThr - 1) / nThr;
    const int nbW  = (L_LAYERS * HDIM * HDIM + nThr - 1) / nThr;
    const dim3 gemmH(HDIM / BN, (N_NODES + BM - 1) / BM);
    const dim3 gemmC(1, (N_NODES + BM - 1) / BM);
    const dim3 mmaGrid(2, (N_NODES + 127) / 128);   // (2, 391)
    const int aggBlocks = 1480;

    weight_prep_kernel<<<nbW, nThr>>>(convW, p_wth, p_wtl);
    softmax_w_kernel<<<1, 1>>>(layer_w, p_w);
    zero_acc_kernel<<<nbNH, nThr>>>(p_acc);
    gemm_bias_kernel<<<gemmH, nThr>>>(x, in_W, in_b, nullptr, p_h,
                                      N_NODES, HDIM, F_INPUT);
    split_kernel<<<nbNH, nThr>>>(p_h, p_hbh, p_hbl);

    zero_cnt_kernel<<<nbN, nThr>>>(p_cnt);
    hist_kernel<<<nbE, nThr>>>(e1 + E_EDGES, p_cnt);
    scan_kernel<<<1, 1024>>>(p_cnt, p_rp1);
    dinv_from_rp_kernel<<<nbN, nThr>>>(p_rp1, p_dinv1);
    cursor_copy_kernel<<<nbN, nThr>>>(p_rp1, p_cur);
    fill_kernel<<<nbE, nThr>>>(e1, e1 + E_EDGES, p_cur, p_csr1);

    zero_cnt_kernel<<<nbN, nThr>>>(p_cnt);
    hist_kernel<<<nbE, nThr>>>(e2 + E_EDGES, p_cnt);
    scan_kernel<<<1, 1024>>>(p_cnt, p_rp2);
    dinv_from_rp_kernel<<<nbN, nThr>>>(p_rp2, p_dinv2);
    cursor_copy_kernel<<<nbN, nThr>>>(p_rp2, p_cur);
    fill_kernel<<<nbE, nThr>>>(e2, e2 + E_EDGES, p_cur, p_csr2);

    for (int l = 0; l < L_LAYERS; l++) {
        const int*   rp   = (l < L_LAYERS / 2) ? p_rp1 : p_rp2;
        const int*   csr  = (l < L_LAYERS / 2) ? p_csr1 : p_csr2;
        const float* dinv = (l < L_LAYERS / 2) ? p_dinv1 : p_dinv2;

        // t' = (h @ convW[l] + convB[l]) * dinv[row] — tensor cores (mma.sync)
        mma_gemm_kernel<<<mmaGrid, nThr>>>(
            p_hbh, p_hbl,
            p_wth + (size_t)l * HDIM * HDIM, p_wtl + (size_t)l * HDIM * HDIM,
            convB + l * HDIM, dinv, p_t, N_NODES);
        // h = dinv * (t'_self + sum of in-neighbors), fused BN stats
        zero_stats_kernel<<<1, HDIM>>>(p_sum, p_sumsq);
        agg_kernel<<<aggBlocks, nThr>>>(rp, csr, dinv, p_t, p_h, p_sum, p_sumsq);
        // BN apply + ReLU + residual; emits bf16 split for the next GEMM
        bn_apply_kernel<<<nbNH, nThr>>>(p_h, p_acc, p_hbh, p_hbl, p_sum, p_sumsq,
                                        bng + l * HDIM, bnb + l * HDIM, p_w, l);
    }

    gemm_bias_kernel<<<gemmC, nThr>>>(p_acc, out_W, out_b, nullptr, p_logits,
                                      N_NODES, C_OUT, HDIM);
    logsoftmax_kernel<<<(N_NODES + 7) / 8, nThr>>>(p_logits, out);
}

// round 6
// speedup vs baseline: 4.5554x; 1.2750x over previous
#include <cuda_runtime.h>
#include <cuda_bf16.h>
#include <math.h>
#include <stdint.h>

#define N_NODES 50000
#define E_EDGES 800000
#define F_INPUT 128
#define HDIM    256
#define C_OUT   112
#define L_LAYERS 8
#define BN_EPS  1e-5f

// ---------------- scratch (device globals; no allocations anywhere) --------
__device__ float g_h[N_NODES * HDIM];
__device__ float g_t[N_NODES * HDIM];
__device__ float g_acc[N_NODES * HDIM];
__device__ float g_logits[N_NODES * C_OUT];
__device__ __nv_bfloat16 g_hbh[N_NODES * HDIM];
__device__ __nv_bfloat16 g_hbl[N_NODES * HDIM];
__device__ __nv_bfloat16 g_wth[L_LAYERS * HDIM * HDIM];  // W^T hi [l][n][k]
__device__ __nv_bfloat16 g_wtl[L_LAYERS * HDIM * HDIM];  // W^T lo
__device__ float g_dinv1[N_NODES];
__device__ float g_dinv2[N_NODES];
__device__ float g_sums[L_LAYERS * HDIM];
__device__ float g_sqs[L_LAYERS * HDIM];
__device__ float g_w[L_LAYERS];
__device__ int g_cnt[N_NODES];
__device__ int g_rp1[N_NODES + 1];
__device__ int g_rp2[N_NODES + 1];
__device__ int g_cur[N_NODES];
__device__ int g_csr1[E_EDGES];
__device__ int g_csr2[E_EDGES];

// ---------------- helpers ---------------------------------------------------
__device__ __forceinline__ uint32_t smem_u32(const void* p) {
    uint32_t a;
    asm("{ .reg .u64 t; cvta.to.shared.u64 t, %1; cvt.u32.u64 %0, t; }"
        : "=r"(a) : "l"(p));
    return a;
}
__device__ __forceinline__ unsigned long long pk2(float lo, float hi) {
    unsigned long long r;
    asm("mov.b64 %0, {%1, %2};" : "=l"(r) : "f"(lo), "f"(hi));
    return r;
}
__device__ __forceinline__ void upk2(float& lo, float& hi, unsigned long long v) {
    asm("mov.b64 {%0, %1}, %2;" : "=f"(lo), "=f"(hi) : "l"(v));
}
__device__ __forceinline__ void ffma2(unsigned long long& d,
                                      unsigned long long a, unsigned long long b) {
    asm("fma.rn.f32x2 %0, %1, %2, %0;" : "+l"(d) : "l"(a), "l"(b));
}
__device__ __forceinline__ void ldm_x4(uint32_t& r0, uint32_t& r1,
                                       uint32_t& r2, uint32_t& r3, uint32_t addr) {
    asm volatile("ldmatrix.sync.aligned.m8n8.x4.shared.b16 {%0,%1,%2,%3}, [%4];"
                 : "=r"(r0), "=r"(r1), "=r"(r2), "=r"(r3) : "r"(addr));
}
__device__ __forceinline__ void mma_bf16(float* d, const uint32_t* a,
                                         uint32_t b0, uint32_t b1) {
    asm volatile(
        "mma.sync.aligned.m16n8k16.row.col.f32.bf16.bf16.f32 "
        "{%0,%1,%2,%3}, {%4,%5,%6,%7}, {%8,%9}, {%0,%1,%2,%3};"
        : "+f"(d[0]), "+f"(d[1]), "+f"(d[2]), "+f"(d[3])
        : "r"(a[0]), "r"(a[1]), "r"(a[2]), "r"(a[3]), "r"(b0), "r"(b1));
}
__device__ __forceinline__ void cpa16(uint32_t dst, const void* src) {
    asm volatile("cp.async.cg.shared.global [%0], [%1], 16;"
                 :: "r"(dst), "l"(src));
}

// ---------------- weight transpose + bf16 split ----------------------------
__global__ void weight_prep_kernel(const float* __restrict__ convW,
                                   __nv_bfloat16* wth, __nv_bfloat16* wtl) {
    int i = blockIdx.x * blockDim.x + threadIdx.x;
    if (i >= L_LAYERS * HDIM * HDIM) return;
    int l = i >> 16;
    int n = (i >> 8) & 255;
    int k = i & 255;
    float v = convW[(l << 16) + (k << 8) + n];
    __nv_bfloat16 hi = __float2bfloat16(v);
    wth[i] = hi;
    wtl[i] = __float2bfloat16(v - __bfloat162float(hi));
}

// ---------------- CSR build -------------------------------------------------
__global__ void zero_cnt_kernel(int* cnt) {
    int i = blockIdx.x * blockDim.x + threadIdx.x;
    if (i < N_NODES) cnt[i] = 0;
}
__global__ void hist_kernel(const int* __restrict__ tgt, int* cnt) {
    int i = blockIdx.x * blockDim.x + threadIdx.x;
    if (i < E_EDGES) atomicAdd(&cnt[tgt[i]], 1);
}
__global__ void scan_kernel(const int* __restrict__ cnt, int* rowptr) {
    __shared__ int s[1024];
    const int T = 1024;
    const int CH = (N_NODES + T - 1) / T;
    int t = threadIdx.x;
    int base = t * CH;
    int loc = 0;
    for (int i = 0; i < CH; i++) {
        int idx = base + i;
        if (idx < N_NODES) loc += cnt[idx];
    }
    s[t] = loc;
    __syncthreads();
    for (int off = 1; off < T; off <<= 1) {
        int v = (t >= off) ? s[t - off] : 0;
        __syncthreads();
        s[t] += v;
        __syncthreads();
    }
    int run = s[t] - loc;
    for (int i = 0; i < CH; i++) {
        int idx = base + i;
        if (idx < N_NODES) {
            rowptr[idx] = run;
            run += cnt[idx];
        }
    }
    if (t == T - 1) rowptr[N_NODES] = run;
}
__global__ void dinv_from_rp_kernel(const int* __restrict__ rowptr, float* dinv) {
    int i = blockIdx.x * blockDim.x + threadIdx.x;
    if (i < N_NODES)
        dinv[i] = rsqrtf((float)(rowptr[i + 1] - rowptr[i]) + 1.0f);
}
__global__ void cursor_copy_kernel(const int* __restrict__ rowptr, int* cur) {
    int i = blockIdx.x * blockDim.x + threadIdx.x;
    if (i < N_NODES) cur[i] = rowptr[i];
}
__global__ void fill_kernel(const int* __restrict__ src, const int* __restrict__ tgt,
                            int* cur, int* csr) {
    int i = blockIdx.x * blockDim.x + threadIdx.x;
    if (i < E_EDGES) {
        int pos = atomicAdd(&cur[tgt[i]], 1);
        csr[pos] = src[i];
    }
}

__global__ void softmax_w_kernel(const float* __restrict__ lw, float* w) {
    float m = -1e30f;
    for (int i = 0; i < L_LAYERS; i++) m = fmaxf(m, lw[i]);
    float s = 0.f;
    for (int i = 0; i < L_LAYERS; i++) s += expf(lw[i] - m);
    for (int i = 0; i < L_LAYERS; i++) w[i] = expf(lw[i] - m) / s;
}

// zero acc + all per-layer stats in one launch
__global__ void zero_init_kernel(float* acc, float* sums, float* sqs) {
    int i = blockIdx.x * blockDim.x + threadIdx.x;
    if (i < N_NODES * HDIM) acc[i] = 0.f;
    if (i < L_LAYERS * HDIM) { sums[i] = 0.f; sqs[i] = 0.f; }
}

// ---------------- SIMT FFMA2 GEMM (in/out FC) ------------------------------
// If hbh != nullptr, writes bf16 hi/lo split of the result instead of C.
#define BM 128
#define BN 128
#define BK 16
__global__ __launch_bounds__(256, 2)
void gemm_bias_kernel(const float* __restrict__ A, const float* __restrict__ B,
                      const float* __restrict__ bias,
                      float* __restrict__ C,
                      __nv_bfloat16* __restrict__ hbh,
                      __nv_bfloat16* __restrict__ hbl,
                      int M, int Nc, int K) {
    __shared__ float As[2][BK][BM + 4];
    __shared__ float Bs[2][BK][BN];
    const int tid  = threadIdx.x;
    const int tRow = tid >> 4;
    const int tCol = tid & 15;
    const int brow = blockIdx.y * BM;
    const int bcol = blockIdx.x * BN;
    const int am0 = tid >> 2;
    const int am1 = (tid + 256) >> 2;
    const int ak  = (tid & 3) * 4;
    const int arow0 = min(brow + am0, M - 1);
    const int arow1 = min(brow + am1, M - 1);
    const int bk0 = tid >> 5;
    const int bk1 = bk0 + 8;
    const int bnx = (tid & 31) * 4;
    const bool bok = (bcol + bnx + 3) < Nc;
    const int bcl  = bok ? (bcol + bnx) : 0;

    unsigned long long acc[8][4];
#pragma unroll
    for (int i = 0; i < 8; i++)
#pragma unroll
        for (int j = 0; j < 4; j++) acc[i][j] = 0ull;

    float4 aR0, aR1, bR0, bR1;
    const float4 z4 = make_float4(0.f, 0.f, 0.f, 0.f);
    aR0 = *(const float4*)(A + (size_t)arow0 * K + ak);
    aR1 = *(const float4*)(A + (size_t)arow1 * K + ak);
    bR0 = bok ? *(const float4*)(B + (size_t)bk0 * Nc + bcl) : z4;
    bR1 = bok ? *(const float4*)(B + (size_t)bk1 * Nc + bcl) : z4;
    As[0][ak + 0][am0] = aR0.x; As[0][ak + 1][am0] = aR0.y;
    As[0][ak + 2][am0] = aR0.z; As[0][ak + 3][am0] = aR0.w;
    As[0][ak + 0][am1] = aR1.x; As[0][ak + 1][am1] = aR1.y;
    As[0][ak + 2][am1] = aR1.z; As[0][ak + 3][am1] = aR1.w;
    *(float4*)&Bs[0][bk0][bnx] = bR0;
    *(float4*)&Bs[0][bk1][bnx] = bR1;
    __syncthreads();

    const int nt = K / BK;
    for (int kt = 0; kt < nt; kt++) {
        const int buf = kt & 1;
        const int nxt = kt + 1;
        if (nxt < nt) {
            const int k0 = nxt * BK;
            aR0 = *(const float4*)(A + (size_t)arow0 * K + k0 + ak);
            aR1 = *(const float4*)(A + (size_t)arow1 * K + k0 + ak);
            bR0 = bok ? *(const float4*)(B + (size_t)(k0 + bk0) * Nc + bcl) : z4;
            bR1 = bok ? *(const float4*)(B + (size_t)(k0 + bk1) * Nc + bcl) : z4;
        }
#pragma unroll
        for (int k = 0; k < BK; k++) {
            float4 a0 = *(const float4*)&As[buf][k][tRow * 4];
            float4 a1 = *(const float4*)&As[buf][k][64 + tRow * 4];
            float4 b0 = *(const float4*)&Bs[buf][k][tCol * 4];
            float4 b1 = *(const float4*)&Bs[buf][k][64 + tCol * 4];
            unsigned long long bb[4] = {pk2(b0.x, b0.y), pk2(b0.z, b0.w),
                                        pk2(b1.x, b1.y), pk2(b1.z, b1.w)};
            float av[8] = {a0.x, a0.y, a0.z, a0.w, a1.x, a1.y, a1.z, a1.w};
#pragma unroll
            for (int i = 0; i < 8; i++) {
                unsigned long long ap = pk2(av[i], av[i]);
#pragma unroll
                for (int j = 0; j < 4; j++) ffma2(acc[i][j], ap, bb[j]);
            }
        }
        if (nxt < nt) {
            const int nb = nxt & 1;
            As[nb][ak + 0][am0] = aR0.x; As[nb][ak + 1][am0] = aR0.y;
            As[nb][ak + 2][am0] = aR0.z; As[nb][ak + 3][am0] = aR0.w;
            As[nb][ak + 0][am1] = aR1.x; As[nb][ak + 1][am1] = aR1.y;
            As[nb][ak + 2][am1] = aR1.z; As[nb][ak + 3][am1] = aR1.w;
            *(float4*)&Bs[nb][bk0][bnx] = bR0;
            *(float4*)&Bs[nb][bk1][bnx] = bR1;
        }
        __syncthreads();
    }

#pragma unroll
    for (int ih = 0; ih < 2; ih++) {
#pragma unroll
        for (int i = 0; i < 4; i++) {
            int r = brow + ih * 64 + tRow * 4 + i;
            if (r >= M) continue;
#pragma unroll
            for (int jh = 0; jh < 2; jh++) {
                int c = bcol + jh * 64 + tCol * 4;
                if (c + 3 < Nc) {
                    float e0, e1, e2, e3;
                    upk2(e0, e1, acc[ih * 4 + i][jh * 2 + 0]);
                    upk2(e2, e3, acc[ih * 4 + i][jh * 2 + 1]);
                    float o0 = e0 + bias[c + 0];
                    float o1 = e1 + bias[c + 1];
                    float o2 = e2 + bias[c + 2];
                    float o3 = e3 + bias[c + 3];
                    if (hbh) {
                        __nv_bfloat16 h0 = __float2bfloat16(o0);
                        __nv_bfloat16 h1 = __float2bfloat16(o1);
                        __nv_bfloat16 h2 = __float2bfloat16(o2);
                        __nv_bfloat16 h3 = __float2bfloat16(o3);
                        __nv_bfloat162 ph0 = {h0, h1}, ph1 = {h2, h3};
                        __nv_bfloat162 pl0 = {
                            __float2bfloat16(o0 - __bfloat162float(h0)),
                            __float2bfloat16(o1 - __bfloat162float(h1))};
                        __nv_bfloat162 pl1 = {
                            __float2bfloat16(o2 - __bfloat162float(h2)),
                            __float2bfloat16(o3 - __bfloat162float(h3))};
                        *(__nv_bfloat162*)(hbh + (size_t)r * Nc + c)     = ph0;
                        *(__nv_bfloat162*)(hbh + (size_t)r * Nc + c + 2) = ph1;
                        *(__nv_bfloat162*)(hbl + (size_t)r * Nc + c)     = pl0;
                        *(__nv_bfloat162*)(hbl + (size_t)r * Nc + c + 2) = pl1;
                    } else {
                        *(float4*)(C + (size_t)r * Nc + c) = make_float4(o0, o1, o2, o3);
                    }
                }
            }
        }
    }
}

// ---------------- mma.sync bf16-split GEMM with cp.async pipeline ----------
// CTA tile 128x128, warp tile 32x64, K chunk 32, double-buffered smem.
#define SROW 40
#define PERBUF (128 * SROW * 2)          // 10240 B: one chunk of one array
#define MG_SMEM (4 * 2 * PERBUF)         // 4 arrays x 2 buffers = 81920 B

__global__ __launch_bounds__(256)
void mma_gemm_kernel(const __nv_bfloat16* __restrict__ Ah,
                     const __nv_bfloat16* __restrict__ Al,
                     const __nv_bfloat16* __restrict__ Bh,
                     const __nv_bfloat16* __restrict__ Bl,
                     const float* __restrict__ bias,
                     const float* __restrict__ dinv,
                     float* __restrict__ C, int M) {
    extern __shared__ char dsm[];
    const uint32_t sb = smem_u32(dsm);
    const int tid  = threadIdx.x;
    const int lane = tid & 31;
    const int wid  = tid >> 5;
    const int wm   = wid & 3;
    const int wn   = wid >> 2;
    const int brow = blockIdx.y * 128;
    const int bcol = blockIdx.x * 128;

    // staging: 512 16B-units per array per chunk; 2 units per thread
    const int r0 = tid >> 2;           // 0..63
    const int r1 = r0 + 64;            // 64..127
    const int sg = tid & 3;
    const int gr0 = min(brow + r0, M - 1);
    const int gr1 = min(brow + r1, M - 1);
    const int wn0 = bcol + r0;
    const int wn1 = bcol + r1;
    const uint32_t d0 = (uint32_t)(r0 * SROW + sg * 8) * 2;
    const uint32_t d1 = (uint32_t)(r1 * SROW + sg * 8) * 2;

    auto issue_chunk = [&](int c) {
        const int kb = c * 32 + sg * 8;
        const uint32_t bo = (uint32_t)(c & 1) * PERBUF;
        cpa16(sb + 0 * 2 * PERBUF + bo + d0, Ah + (size_t)gr0 * HDIM + kb);
        cpa16(sb + 0 * 2 * PERBUF + bo + d1, Ah + (size_t)gr1 * HDIM + kb);
        cpa16(sb + 1 * 2 * PERBUF + bo + d0, Al + (size_t)gr0 * HDIM + kb);
        cpa16(sb + 1 * 2 * PERBUF + bo + d1, Al + (size_t)gr1 * HDIM + kb);
        cpa16(sb + 2 * 2 * PERBUF + bo + d0, Bh + (size_t)wn0 * HDIM + kb);
        cpa16(sb + 2 * 2 * PERBUF + bo + d1, Bh + (size_t)wn1 * HDIM + kb);
        cpa16(sb + 3 * 2 * PERBUF + bo + d0, Bl + (size_t)wn0 * HDIM + kb);
        cpa16(sb + 3 * 2 * PERBUF + bo + d1, Bl + (size_t)wn1 * HDIM + kb);
        asm volatile("cp.async.commit_group;");
    };

    // ldmatrix lane offsets (relative to array+buffer base)
    const int li = lane & 7;
    const int lb = (lane >> 3) & 1;
    const int lc = (lane >> 4) & 1;
    uint32_t aoff[2], boff[4];
#pragma unroll
    for (int mf = 0; mf < 2; mf++)
        aoff[mf] = (uint32_t)((wm * 32 + mf * 16 + lb * 8 + li) * SROW + lc * 8) * 2;
#pragma unroll
    for (int nf = 0; nf < 4; nf++)
        boff[nf] = (uint32_t)((wn * 64 + nf * 16 + lc * 8 + li) * SROW + lb * 8) * 2;

    float acc[2][8][4];
#pragma unroll
    for (int i = 0; i < 2; i++)
#pragma unroll
        for (int j = 0; j < 8; j++)
#pragma unroll
            for (int k = 0; k < 4; k++) acc[i][j][k] = 0.f;

    issue_chunk(0);
    for (int c = 0; c < 8; c++) {
        asm volatile("cp.async.wait_group 0;" ::: "memory");
        __syncthreads();           // chunk c landed; everyone done with other buf
        if (c < 7) issue_chunk(c + 1);
        const uint32_t bo = (uint32_t)(c & 1) * PERBUF;
        const uint32_t bAh = sb + 0 * 2 * PERBUF + bo;
        const uint32_t bAl = sb + 1 * 2 * PERBUF + bo;
        const uint32_t bBh = sb + 2 * 2 * PERBUF + bo;
        const uint32_t bBl = sb + 3 * 2 * PERBUF + bo;

#pragma unroll
        for (int ks = 0; ks < 2; ks++) {
            const uint32_t kadd = ks * 32;
            uint32_t A0h[4], A1h[4], A0l[4], A1l[4];
            ldm_x4(A0h[0], A0h[1], A0h[2], A0h[3], bAh + aoff[0] + kadd);
            ldm_x4(A1h[0], A1h[1], A1h[2], A1h[3], bAh + aoff[1] + kadd);
            ldm_x4(A0l[0], A0l[1], A0l[2], A0l[3], bAl + aoff[0] + kadd);
            ldm_x4(A1l[0], A1l[1], A1l[2], A1l[3], bAl + aoff[1] + kadd);
#pragma unroll
            for (int nf = 0; nf < 4; nf++) {
                uint32_t bh[4], bl[4];
                ldm_x4(bh[0], bh[1], bh[2], bh[3], bBh + boff[nf] + kadd);
                ldm_x4(bl[0], bl[1], bl[2], bl[3], bBl + boff[nf] + kadd);
                mma_bf16(acc[0][nf * 2 + 0], A0h, bh[0], bh[1]);
                mma_bf16(acc[0][nf * 2 + 0], A0h, bl[0], bl[1]);
                mma_bf16(acc[0][nf * 2 + 0], A0l, bh[0], bh[1]);
                mma_bf16(acc[0][nf * 2 + 1], A0h, bh[2], bh[3]);
                mma_bf16(acc[0][nf * 2 + 1], A0h, bl[2], bl[3]);
                mma_bf16(acc[0][nf * 2 + 1], A0l, bh[2], bh[3]);
                mma_bf16(acc[1][nf * 2 + 0], A1h, bh[0], bh[1]);
                mma_bf16(acc[1][nf * 2 + 0], A1h, bl[0], bl[1]);
                mma_bf16(acc[1][nf * 2 + 0], A1l, bh[0], bh[1]);
                mma_bf16(acc[1][nf * 2 + 1], A1h, bh[2], bh[3]);
                mma_bf16(acc[1][nf * 2 + 1], A1h, bl[2], bl[3]);
                mma_bf16(acc[1][nf * 2 + 1], A1l, bh[2], bh[3]);
            }
        }
        __syncthreads();           // ldmatrix reads of buf c done before refill
    }

    // epilogue: C[r, c] = (acc + bias[c]) * dinv[r]
    const int qr = lane >> 2;
    const int qc = (lane & 3) * 2;
#pragma unroll
    for (int mf = 0; mf < 2; mf++) {
        int rr0 = brow + wm * 32 + mf * 16 + qr;
        int rr1 = rr0 + 8;
        float dv0 = (rr0 < M) ? dinv[rr0] : 0.f;
        float dv1 = (rr1 < M) ? dinv[rr1] : 0.f;
#pragma unroll
        for (int nf = 0; nf < 8; nf++) {
            int cc = bcol + wn * 64 + nf * 8 + qc;
            float b0 = bias[cc], b1 = bias[cc + 1];
            if (rr0 < M) {
                float2 o = make_float2((acc[mf][nf][0] + b0) * dv0,
                                       (acc[mf][nf][1] + b1) * dv0);
                *(float2*)(C + (size_t)rr0 * HDIM + cc) = o;
            }
            if (rr1 < M) {
                float2 o = make_float2((acc[mf][nf][2] + b0) * dv1,
                                       (acc[mf][nf][3] + b1) * dv1);
                *(float2*)(C + (size_t)rr1 * HDIM + cc) = o;
            }
        }
    }
}

// ---------------- CSR aggregation + fused BN stats --------------------------
__global__ __launch_bounds__(256)
void agg_kernel(const int* __restrict__ rowptr, const int* __restrict__ csr,
                const float* __restrict__ dinv, const float* __restrict__ tp,
                float* __restrict__ h, float* gsum, float* gsq) {
    __shared__ float s_sum[HDIM];
    __shared__ float s_sq[HDIM];
    int tid  = threadIdx.x;
    int lane = tid & 31;
    int warp = tid >> 5;
    int gw   = blockIdx.x * 8 + warp;
    int nw   = gridDim.x * 8;

    s_sum[tid] = 0.f;
    s_sq[tid]  = 0.f;

    float ssum[8], ssq[8];
#pragma unroll
    for (int i = 0; i < 8; i++) { ssum[i] = 0.f; ssq[i] = 0.f; }

    for (int v = gw; v < N_NODES; v += nw) {
        const float4* self = (const float4*)(tp + (size_t)v * HDIM);
        float4 a0 = self[lane];
        float4 a1 = self[lane + 32];
        int beg = rowptr[v], end = rowptr[v + 1];
        int e = beg;
        for (; e + 1 < end; e += 2) {
            int s0 = csr[e], s1 = csr[e + 1];
            const float4* r0 = (const float4*)(tp + (size_t)s0 * HDIM);
            const float4* r1 = (const float4*)(tp + (size_t)s1 * HDIM);
            float4 v00 = r0[lane], v01 = r0[lane + 32];
            float4 v10 = r1[lane], v11 = r1[lane + 32];
            a0.x += v00.x + v10.x; a0.y += v00.y + v10.y;
            a0.z += v00.z + v10.z; a0.w += v00.w + v10.w;
            a1.x += v01.x + v11.x; a1.y += v01.y + v11.y;
            a1.z += v01.z + v11.z; a1.w += v01.w + v11.w;
        }
        if (e < end) {
            int s0 = csr[e];
            const float4* r0 = (const float4*)(tp + (size_t)s0 * HDIM);
            float4 v00 = r0[lane], v01 = r0[lane + 32];
            a0.x += v00.x; a0.y += v00.y; a0.z += v00.z; a0.w += v00.w;
            a1.x += v01.x; a1.y += v01.y; a1.z += v01.z; a1.w += v01.w;
        }
        float dv = dinv[v];
        a0.x *= dv; a0.y *= dv; a0.z *= dv; a0.w *= dv;
        a1.x *= dv; a1.y *= dv; a1.z *= dv; a1.w *= dv;
        float4* hrow = (float4*)(h + (size_t)v * HDIM);
        hrow[lane]      = a0;
        hrow[lane + 32] = a1;
        ssum[0] += a0.x; ssum[1] += a0.y; ssum[2] += a0.z; ssum[3] += a0.w;
        ssum[4] += a1.x; ssum[5] += a1.y; ssum[6] += a1.z; ssum[7] += a1.w;
        ssq[0] += a0.x * a0.x; ssq[1] += a0.y * a0.y;
        ssq[2] += a0.z * a0.z; ssq[3] += a0.w * a0.w;
        ssq[4] += a1.x * a1.x; ssq[5] += a1.y * a1.y;
        ssq[6] += a1.z * a1.z; ssq[7] += a1.w * a1.w;
    }
    __syncthreads();
#pragma unroll
    for (int k = 0; k < 4; k++) {
        atomicAdd(&s_sum[lane * 4 + k], ssum[k]);
        atomicAdd(&s_sum[128 + lane * 4 + k], ssum[4 + k]);
        atomicAdd(&s_sq[lane * 4 + k], ssq[k]);
        atomicAdd(&s_sq[128 + lane * 4 + k], ssq[4 + k]);
    }
    __syncthreads();
    atomicAdd(&gsum[tid], s_sum[tid]);
    atomicAdd(&gsq[tid], s_sq[tid]);
}

// ---------------- BN apply + ReLU + residual (float4) -----------------------
__global__ void bn_apply_kernel(const float4* __restrict__ h,
                                float4* __restrict__ acc,
                                __nv_bfloat16* __restrict__ hbh,
                                __nv_bfloat16* __restrict__ hbl,
                                const float* __restrict__ sum,
                                const float* __restrict__ sumsq,
                                const float* __restrict__ gamma,
                                const float* __restrict__ beta,
                                const float* __restrict__ w, int layer) {
    int idx = blockIdx.x * blockDim.x + threadIdx.x;
    if (idx >= N_NODES * HDIM / 4) return;
    int f4 = idx & 63;   // float4 column index
    const float invN = 1.0f / (float)N_NODES;
    float4 s4 = ((const float4*)sum)[f4];
    float4 q4 = ((const float4*)sumsq)[f4];
    float4 g4 = ((const float4*)gamma)[f4];
    float4 b4 = ((const float4*)beta)[f4];
    float4 hv = h[idx];
    float wl = w[layer];

    float mu, var, v;
    float4 av = acc[idx];
    float4 res;
    __nv_bfloat16 hh[4], ll[4];

    mu = s4.x * invN; var = q4.x * invN - mu * mu;
    v = fmaxf((hv.x - mu) * rsqrtf(var + BN_EPS) * g4.x + b4.x, 0.f);
    av.x += wl * v; hh[0] = __float2bfloat16(v);
    ll[0] = __float2bfloat16(v - __bfloat162float(hh[0])); res.x = v;

    mu = s4.y * invN; var = q4.y * invN - mu * mu;
    v = fmaxf((hv.y - mu) * rsqrtf(var + BN_EPS) * g4.y + b4.y, 0.f);
    av.y += wl * v; hh[1] = __float2bfloat16(v);
    ll[1] = __float2bfloat16(v - __bfloat162float(hh[1]));

    mu = s4.z * invN; var = q4.z * invN - mu * mu;
    v = fmaxf((hv.z - mu) * rsqrtf(var + BN_EPS) * g4.z + b4.z, 0.f);
    av.z += wl * v; hh[2] = __float2bfloat16(v);
    ll[2] = __float2bfloat16(v - __bfloat162float(hh[2]));

    mu = s4.w * invN; var = q4.w * invN - mu * mu;
    v = fmaxf((hv.w - mu) * rsqrtf(var + BN_EPS) * g4.w + b4.w, 0.f);
    av.w += wl * v; hh[3] = __float2bfloat16(v);
    ll[3] = __float2bfloat16(v - __bfloat162float(hh[3]));

    acc[idx] = av;
    __nv_bfloat162 ph0 = {hh[0], hh[1]}, ph1 = {hh[2], hh[3]};
    __nv_bfloat162 pl0 = {ll[0], ll[1]}, pl1 = {ll[2], ll[3]};
    *(__nv_bfloat162*)(hbh + (size_t)idx * 4)     = ph0;
    *(__nv_bfloat162*)(hbh + (size_t)idx * 4 + 2) = ph1;
    *(__nv_bfloat162*)(hbl + (size_t)idx * 4)     = pl0;
    *(__nv_bfloat162*)(hbl + (size_t)idx * 4 + 2) = pl1;
}

// ---------------- log-softmax -----------------------------------------------
__global__ void logsoftmax_kernel(const float* __restrict__ logits,
                                  float* __restrict__ out) {
    int row  = blockIdx.x * 8 + (threadIdx.x >> 5);
    int lane = threadIdx.x & 31;
    if (row >= N_NODES) return;
    const float* lr = logits + (size_t)row * C_OUT;
    float vals[4];
    int cnt = 0;
    float m = -1e30f;
    for (int f = lane; f < C_OUT; f += 32) {
        vals[cnt] = lr[f];
        m = fmaxf(m, vals[cnt]);
        cnt++;
    }
#pragma unroll
    for (int off = 16; off >= 1; off >>= 1)
        m = fmaxf(m, __shfl_xor_sync(0xffffffffu, m, off));
    float s = 0.f;
    for (int i = 0; i < cnt; i++) s += expf(vals[i] - m);
#pragma unroll
    for (int off = 16; off >= 1; off >>= 1)
        s += __shfl_xor_sync(0xffffffffu, s, off);
    float lse = m + logf(s);
    cnt = 0;
    for (int f = lane; f < C_OUT; f += 32) {
        out[(size_t)row * C_OUT + f] = vals[cnt] - lse;
        cnt++;
    }
}

// ---------------- host launcher ---------------------------------------------
extern "C" void kernel_launch(void* const* d_in, const int* in_sizes, int n_in,
                              void* d_out, int out_size) {
    const float* x       = (const float*)d_in[0];
    const int*   e1      = (const int*)  d_in[1];
    const int*   e2      = (const int*)  d_in[2];
    const float* in_W    = (const float*)d_in[3];
    const float* in_b    = (const float*)d_in[4];
    const float* convW   = (const float*)d_in[5];
    const float* convB   = (const float*)d_in[6];
    const float* bng     = (const float*)d_in[7];
    const float* bnb     = (const float*)d_in[8];
    const float* out_W   = (const float*)d_in[9];
    const float* out_b   = (const float*)d_in[10];
    const float* layer_w = (const float*)d_in[11];
    float* out = (float*)d_out;

    float *p_h, *p_t, *p_acc, *p_logits, *p_dinv1, *p_dinv2, *p_sums, *p_sqs, *p_w;
    __nv_bfloat16 *p_hbh, *p_hbl, *p_wth, *p_wtl;
    int *p_cnt, *p_rp1, *p_rp2, *p_cur, *p_csr1, *p_csr2;
    cudaGetSymbolAddress((void**)&p_h, g_h);
    cudaGetSymbolAddress((void**)&p_t, g_t);
    cudaGetSymbolAddress((void**)&p_acc, g_acc);
    cudaGetSymbolAddress((void**)&p_logits, g_logits);
    cudaGetSymbolAddress((void**)&p_hbh, g_hbh);
    cudaGetSymbolAddress((void**)&p_hbl, g_hbl);
    cudaGetSymbolAddress((void**)&p_wth, g_wth);
    cudaGetSymbolAddress((void**)&p_wtl, g_wtl);
    cudaGetSymbolAddress((void**)&p_dinv1, g_dinv1);
    cudaGetSymbolAddress((void**)&p_dinv2, g_dinv2);
    cudaGetSymbolAddress((void**)&p_sums, g_sums);
    cudaGetSymbolAddress((void**)&p_sqs, g_sqs);
    cudaGetSymbolAddress((void**)&p_w, g_w);
    cudaGetSymbolAddress((void**)&p_cnt, g_cnt);
    cudaGetSymbolAddress((void**)&p_rp1, g_rp1);
    cudaGetSymbolAddress((void**)&p_rp2, g_rp2);
    cudaGetSymbolAddress((void**)&p_cur, g_cur);
    cudaGetSymbolAddress((void**)&p_csr1, g_csr1);
    cudaGetSymbolAddress((void**)&p_csr2, g_csr2);

    cudaFuncSetAttribute(mma_gemm_kernel,
                         cudaFuncAttributeMaxDynamicSharedMemorySize, MG_SMEM);

    const int nThr = 256;
    const int nbN  = (N_NODES + nThr - 1) / nThr;
    const int nbE  = (E_EDGES + nThr - 1) / nThr;
    const int nbNH = (N_NODES * HDIM + nThr - 1) / nThr;
    const int nbNH4 = (N_NODES * HDIM / 4 + nThr - 1) / nThr;
    const int nbW  = (L_LAYERS * HDIM * HDIM + nThr - 1) / nThr;
    const dim3 gemmH(HDIM / BN, (N_NODES + BM - 1) / BM);
    const dim3 gemmC(1, (N_NODES + BM - 1) / BM);
    const dim3 mmaGrid(2, (N_NODES + 127) / 128);
    const int aggBlocks = 1480;

    weight_prep_kernel<<<nbW, nThr>>>(convW, p_wth, p_wtl);
    softmax_w_kernel<<<1, 1>>>(layer_w, p_w);
    zero_init_kernel<<<nbNH, nThr>>>(p_acc, p_sums, p_sqs);
    // input FC writes the bf16 hi/lo split directly (no fp32 h, no split pass)
    gemm_bias_kernel<<<gemmH, nThr>>>(x, in_W, in_b, nullptr, p_hbh, p_hbl,
                                      N_NODES, HDIM, F_INPUT);

    zero_cnt_kernel<<<nbN, nThr>>>(p_cnt);
    hist_kernel<<<nbE, nThr>>>(e1 + E_EDGES, p_cnt);
    scan_kernel<<<1, 1024>>>(p_cnt, p_rp1);
    dinv_from_rp_kernel<<<nbN, nThr>>>(p_rp1, p_dinv1);
    cursor_copy_kernel<<<nbN, nThr>>>(p_rp1, p_cur);
    fill_kernel<<<nbE, nThr>>>(e1, e1 + E_EDGES, p_cur, p_csr1);

    zero_cnt_kernel<<<nbN, nThr>>>(p_cnt);
    hist_kernel<<<nbE, nThr>>>(e2 + E_EDGES, p_cnt);
    scan_kernel<<<1, 1024>>>(p_cnt, p_rp2);
    dinv_from_rp_kernel<<<nbN, nThr>>>(p_rp2, p_dinv2);
    cursor_copy_kernel<<<nbN, nThr>>>(p_rp2, p_cur);
    fill_kernel<<<nbE, nThr>>>(e2, e2 + E_EDGES, p_cur, p_csr2);

    for (int l = 0; l < L_LAYERS; l++) {
        const int*   rp   = (l < L_LAYERS / 2) ? p_rp1 : p_rp2;
        const int*   csr  = (l < L_LAYERS / 2) ? p_csr1 : p_csr2;
        const float* dinv = (l < L_LAYERS / 2) ? p_dinv1 : p_dinv2;

        mma_gemm_kernel<<<mmaGrid, nThr, MG_SMEM>>>(
            p_hbh, p_hbl,
            p_wth + (size_t)l * HDIM * HDIM, p_wtl + (size_t)l * HDIM * HDIM,
            convB + l * HDIM, dinv, p_t, N_NODES);
        agg_kernel<<<aggBlocks, nThr>>>(rp, csr, dinv, p_t, p_h,
                                        p_sums + l * HDIM, p_sqs + l * HDIM);
        bn_apply_kernel<<<nbNH4, nThr>>>((const float4*)p_h, (float4*)p_acc,
                                         p_hbh, p_hbl,
                                         p_sums + l * HDIM, p_sqs + l * HDIM,
                                         bng + l * HDIM, bnb + l * HDIM, p_w, l);
    }

    gemm_bias_kernel<<<gemmC, nThr>>>(p_acc, out_W, out_b, p_logits, nullptr, nullptr,
                                      N_NODES, C_OUT, HDIM);
    logsoftmax_kernel<<<(N_NODES + 7) / 8, nThr>>>(p_logits, out);
}

// round 8
// speedup vs baseline: 5.1740x; 1.1358x over previous
#include <cuda_runtime.h>
#include <cuda_bf16.h>
#include <math.h>
#include <stdint.h>

#define N_NODES 50000
#define E_EDGES 800000
#define F_INPUT 128
#define HDIM    256
#define C_OUT   112
#define L_LAYERS 8
#define BN_EPS  1e-5f

// ---------------- scratch (device globals; no allocations anywhere) --------
__device__ float g_h0[N_NODES * HDIM];                       // input FC output
__device__ float g_t[N_NODES * HDIM];                        // t' per layer
__device__ float g_hist[L_LAYERS * N_NODES * HDIM];          // raw agg out per layer
__device__ float g_comb[N_NODES * HDIM];                     // sum w_l relu(bn(h_l))
__device__ __nv_bfloat16 g_wth[L_LAYERS * HDIM * HDIM];      // W^T hi [l][n][k]
__device__ __nv_bfloat16 g_wtl[L_LAYERS * HDIM * HDIM];      // W^T lo
__device__ float g_dinv1[N_NODES];
__device__ float g_dinv2[N_NODES];
__device__ float g_sums[L_LAYERS * HDIM];
__device__ float g_sqs[L_LAYERS * HDIM];
__device__ float g_w[L_LAYERS];
__device__ int g_cnt1[N_NODES];
__device__ int g_cnt2[N_NODES];
__device__ int g_rp1[N_NODES + 1];
__device__ int g_rp2[N_NODES + 1];
__device__ int g_cur1[N_NODES];
__device__ int g_cur2[N_NODES];
__device__ int g_csr1[E_EDGES];
__device__ int g_csr2[E_EDGES];

// ---------------- helpers ---------------------------------------------------
__device__ __forceinline__ uint32_t smem_u32(const void* p) {
    uint32_t a;
    asm("{ .reg .u64 t; cvta.to.shared.u64 t, %1; cvt.u32.u64 %0, t; }"
        : "=r"(a) : "l"(p));
    return a;
}
__device__ __forceinline__ unsigned long long pk2(float lo, float hi) {
    unsigned long long r;
    asm("mov.b64 %0, {%1, %2};" : "=l"(r) : "f"(lo), "f"(hi));
    return r;
}
__device__ __forceinline__ void upk2(float& lo, float& hi, unsigned long long v) {
    asm("mov.b64 {%0, %1}, %2;" : "=f"(lo), "=f"(hi) : "l"(v));
}
__device__ __forceinline__ void ffma2(unsigned long long& d,
                                      unsigned long long a, unsigned long long b) {
    asm("fma.rn.f32x2 %0, %1, %2, %0;" : "+l"(d) : "l"(a), "l"(b));
}
__device__ __forceinline__ void ldm_x4(uint32_t& r0, uint32_t& r1,
                                       uint32_t& r2, uint32_t& r3, uint32_t addr) {
    asm volatile("ldmatrix.sync.aligned.m8n8.x4.shared.b16 {%0,%1,%2,%3}, [%4];"
                 : "=r"(r0), "=r"(r1), "=r"(r2), "=r"(r3) : "r"(addr));
}
__device__ __forceinline__ void mma_bf16(float* d, const uint32_t* a,
                                         uint32_t b0, uint32_t b1) {
    asm volatile(
        "mma.sync.aligned.m16n8k16.row.col.f32.bf16.bf16.f32 "
        "{%0,%1,%2,%3}, {%4,%5,%6,%7}, {%8,%9}, {%0,%1,%2,%3};"
        : "+f"(d[0]), "+f"(d[1]), "+f"(d[2]), "+f"(d[3])
        : "r"(a[0]), "r"(a[1]), "r"(a[2]), "r"(a[3]), "r"(b0), "r"(b1));
}
__device__ __forceinline__ void cpa16(uint32_t dst, const void* src) {
    asm volatile("cp.async.cg.shared.global [%0], [%1], 16;"
                 :: "r"(dst), "l"(src));
}
__device__ __forceinline__ uint32_t bf2pack(__nv_bfloat16 a, __nv_bfloat16 b) {
    __nv_bfloat162 p = {a, b};
    return *(uint32_t*)&p;
}

// ---------------- prep: weight transpose/split + zero stats + softmax(w) ---
__global__ void prep_kernel(const float* __restrict__ convW,
                            const float* __restrict__ lw,
                            __nv_bfloat16* wth, __nv_bfloat16* wtl,
                            float* sums, float* sqs, float* w) {
    int i = blockIdx.x * blockDim.x + threadIdx.x;
    if (i < L_LAYERS * HDIM) { sums[i] = 0.f; sqs[i] = 0.f; }
    if (i == 0) {
        float m = -1e30f;
        for (int l = 0; l < L_LAYERS; l++) m = fmaxf(m, lw[l]);
        float s = 0.f;
        for (int l = 0; l < L_LAYERS; l++) s += expf(lw[l] - m);
        for (int l = 0; l < L_LAYERS; l++) w[l] = expf(lw[l] - m) / s;
    }
    if (i >= L_LAYERS * HDIM * HDIM) return;
    int l = i >> 16;
    int n = (i >> 8) & 255;
    int k = i & 255;
    float v = convW[(l << 16) + (k << 8) + n];
    __nv_bfloat16 hi = __float2bfloat16(v);
    wth[i] = hi;
    wtl[i] = __float2bfloat16(v - __bfloat162float(hi));
}

// ---------------- CSR build (both adjacencies per launch) -------------------
__global__ void zero2_kernel(int* c1, int* c2) {
    int i = blockIdx.x * blockDim.x + threadIdx.x;
    if (i < N_NODES) { c1[i] = 0; c2[i] = 0; }
}
__global__ void hist2_kernel(const int* __restrict__ t1, const int* __restrict__ t2,
                             int* c1, int* c2) {
    int i = blockIdx.x * blockDim.x + threadIdx.x;
    if (i < E_EDGES) {
        atomicAdd(&c1[t1[i]], 1);
        atomicAdd(&c2[t2[i]], 1);
    }
}
__global__ void scan2_kernel(const int* __restrict__ c1, const int* __restrict__ c2,
                             int* r1, int* r2) {
    __shared__ int s[1024];
    const int* cnt = blockIdx.x ? c2 : c1;
    int* rowptr    = blockIdx.x ? r2 : r1;
    const int T = 1024;
    const int CH = (N_NODES + T - 1) / T;
    int t = threadIdx.x;
    int base = t * CH;
    int loc = 0;
    for (int i = 0; i < CH; i++) {
        int idx = base + i;
        if (idx < N_NODES) loc += cnt[idx];
    }
    s[t] = loc;
    __syncthreads();
    for (int off = 1; off < T; off <<= 1) {
        int v = (t >= off) ? s[t - off] : 0;
        __syncthreads();
        s[t] += v;
        __syncthreads();
    }
    int run = s[t] - loc;
    for (int i = 0; i < CH; i++) {
        int idx = base + i;
        if (idx < N_NODES) {
            rowptr[idx] = run;
            run += cnt[idx];
        }
    }
    if (t == T - 1) rowptr[N_NODES] = run;
}
__global__ void dinvcur2_kernel(const int* __restrict__ r1, const int* __restrict__ r2,
                                float* d1, float* d2, int* cu1, int* cu2) {
    int i = blockIdx.x * blockDim.x + threadIdx.x;
    if (i < N_NODES) {
        int a = r1[i], b = r1[i + 1];
        d1[i] = rsqrtf((float)(b - a) + 1.0f);
        cu1[i] = a;
        int c = r2[i], d = r2[i + 1];
        d2[i] = rsqrtf((float)(d - c) + 1.0f);
        cu2[i] = c;
    }
}
__global__ void fill2_kernel(const int* __restrict__ e1, const int* __restrict__ e2,
                             int* cu1, int* cu2, int* cs1, int* cs2) {
    int i = blockIdx.x * blockDim.x + threadIdx.x;
    if (i < E_EDGES) {
        int p1 = atomicAdd(&cu1[e1[E_EDGES + i]], 1);
        cs1[p1] = e1[i];
        int p2 = atomicAdd(&cu2[e2[E_EDGES + i]], 1);
        cs2[p2] = e2[i];
    }
}

// ---------------- SIMT FFMA2 GEMM (input FC): C = A@B + bias ----------------
#define BM 128
#define BN 128
#define BK 16
__global__ __launch_bounds__(256, 2)
void gemm_bias_kernel(const float* __restrict__ A, const float* __restrict__ B,
                      const float* __restrict__ bias, float* __restrict__ C,
                      int M, int Nc, int K) {
    __shared__ float As[2][BK][BM + 4];
    __shared__ float Bs[2][BK][BN];
    const int tid  = threadIdx.x;
    const int tRow = tid >> 4;
    const int tCol = tid & 15;
    const int brow = blockIdx.y * BM;
    const int bcol = blockIdx.x * BN;
    const int am0 = tid >> 2;
    const int am1 = (tid + 256) >> 2;
    const int ak  = (tid & 3) * 4;
    const int arow0 = min(brow + am0, M - 1);
    const int arow1 = min(brow + am1, M - 1);
    const int bk0 = tid >> 5;
    const int bk1 = bk0 + 8;
    const int bnx = (tid & 31) * 4;
    const bool bok = (bcol + bnx + 3) < Nc;
    const int bcl  = bok ? (bcol + bnx) : 0;

    unsigned long long acc[8][4];
#pragma unroll
    for (int i = 0; i < 8; i++)
#pragma unroll
        for (int j = 0; j < 4; j++) acc[i][j] = 0ull;

    float4 aR0, aR1, bR0, bR1;
    const float4 z4 = make_float4(0.f, 0.f, 0.f, 0.f);
    aR0 = *(const float4*)(A + (size_t)arow0 * K + ak);
    aR1 = *(const float4*)(A + (size_t)arow1 * K + ak);
    bR0 = bok ? *(const float4*)(B + (size_t)bk0 * Nc + bcl) : z4;
    bR1 = bok ? *(const float4*)(B + (size_t)bk1 * Nc + bcl) : z4;
    As[0][ak + 0][am0] = aR0.x; As[0][ak + 1][am0] = aR0.y;
    As[0][ak + 2][am0] = aR0.z; As[0][ak + 3][am0] = aR0.w;
    As[0][ak + 0][am1] = aR1.x; As[0][ak + 1][am1] = aR1.y;
    As[0][ak + 2][am1] = aR1.z; As[0][ak + 3][am1] = aR1.w;
    *(float4*)&Bs[0][bk0][bnx] = bR0;
    *(float4*)&Bs[0][bk1][bnx] = bR1;
    __syncthreads();

    const int nt = K / BK;
    for (int kt = 0; kt < nt; kt++) {
        const int buf = kt & 1;
        const int nxt = kt + 1;
        if (nxt < nt) {
            const int k0 = nxt * BK;
            aR0 = *(const float4*)(A + (size_t)arow0 * K + k0 + ak);
            aR1 = *(const float4*)(A + (size_t)arow1 * K + k0 + ak);
            bR0 = bok ? *(const float4*)(B + (size_t)(k0 + bk0) * Nc + bcl) : z4;
            bR1 = bok ? *(const float4*)(B + (size_t)(k0 + bk1) * Nc + bcl) : z4;
        }
#pragma unroll
        for (int k = 0; k < BK; k++) {
            float4 a0 = *(const float4*)&As[buf][k][tRow * 4];
            float4 a1 = *(const float4*)&As[buf][k][64 + tRow * 4];
            float4 b0 = *(const float4*)&Bs[buf][k][tCol * 4];
            float4 b1 = *(const float4*)&Bs[buf][k][64 + tCol * 4];
            unsigned long long bb[4] = {pk2(b0.x, b0.y), pk2(b0.z, b0.w),
                                        pk2(b1.x, b1.y), pk2(b1.z, b1.w)};
            float av[8] = {a0.x, a0.y, a0.z, a0.w, a1.x, a1.y, a1.z, a1.w};
#pragma unroll
            for (int i = 0; i < 8; i++) {
                unsigned long long ap = pk2(av[i], av[i]);
#pragma unroll
                for (int j = 0; j < 4; j++) ffma2(acc[i][j], ap, bb[j]);
            }
        }
        if (nxt < nt) {
            const int nb = nxt & 1;
            As[nb][ak + 0][am0] = aR0.x; As[nb][ak + 1][am0] = aR0.y;
            As[nb][ak + 2][am0] = aR0.z; As[nb][ak + 3][am0] = aR0.w;
            As[nb][ak + 0][am1] = aR1.x; As[nb][ak + 1][am1] = aR1.y;
            As[nb][ak + 2][am1] = aR1.z; As[nb][ak + 3][am1] = aR1.w;
            *(float4*)&Bs[nb][bk0][bnx] = bR0;
            *(float4*)&Bs[nb][bk1][bnx] = bR1;
        }
        __syncthreads();
    }

#pragma unroll
    for (int ih = 0; ih < 2; ih++) {
#pragma unroll
        for (int i = 0; i < 4; i++) {
            int r = brow + ih * 64 + tRow * 4 + i;
            if (r >= M) continue;
#pragma unroll
            for (int jh = 0; jh < 2; jh++) {
                int c = bcol + jh * 64 + tCol * 4;
                if (c + 3 < Nc) {
                    float e0, e1, e2, e3;
                    upk2(e0, e1, acc[ih * 4 + i][jh * 2 + 0]);
                    upk2(e2, e3, acc[ih * 4 + i][jh * 2 + 1]);
                    *(float4*)(C + (size_t)r * Nc + c) =
                        make_float4(e0 + bias[c], e1 + bias[c + 1],
                                    e2 + bias[c + 2], e3 + bias[c + 3]);
                }
            }
        }
    }
}

// ---------------- mma.sync GEMM with fused BN+ReLU+bf16-split A-staging ----
// t = bf16split(relu(bn(Hin))) @ W^T (hi/lo), epilogue *(bias,dinv).
// CTA 128x128, warp 32x64, K chunk 32, A fp32->regs->smem, B via cp.async.
#define SROW 40
#define ABUF (128 * SROW * 2)                 // 10240 B per array per buffer
#define MG_SMEM (8 * ABUF + 2048)             // + bn param tables

__global__ __launch_bounds__(256, 2)
void mma_gemm_kernel(const float* __restrict__ Hin,
                     const float* __restrict__ bsum, const float* __restrict__ bsq,
                     const float* __restrict__ gamma, const float* __restrict__ beta,
                     int do_bn,
                     const __nv_bfloat16* __restrict__ Bh,
                     const __nv_bfloat16* __restrict__ Bl,
                     const float* __restrict__ bias,
                     const float* __restrict__ dinv,
                     float* __restrict__ C, int M) {
    extern __shared__ char dsm[];
    float* sS  = (float*)(dsm + 8 * ABUF);
    float* sSh = sS + 256;
    const uint32_t sb = smem_u32(dsm);
    const int tid  = threadIdx.x;
    const int lane = tid & 31;
    const int wid  = tid >> 5;
    const int wm   = wid & 3;
    const int wn   = wid >> 2;
    const int brow = blockIdx.y * 128;
    const int bcol = blockIdx.x * 128;

    if (tid < 256) {
        if (do_bn) {
            float mu  = bsum[tid] * (1.0f / N_NODES);
            float var = bsq[tid] * (1.0f / N_NODES) - mu * mu;
            float s = gamma[tid] * rsqrtf(var + BN_EPS);
            sS[tid] = s;
            sSh[tid] = beta[tid] - mu * s;
        } else {
            sS[tid] = 1.f;
            sSh[tid] = 0.f;
        }
    }

    const int r0 = tid >> 2, r1 = r0 + 64, sg = tid & 3;
    const int gr0 = min(brow + r0, M - 1);
    const int gr1 = min(brow + r1, M - 1);
    const int wn0 = bcol + r0, wn1 = bcol + r1;
    const uint32_t d0 = (uint32_t)(r0 * SROW + sg * 8) * 2;
    const uint32_t d1 = (uint32_t)(r1 * SROW + sg * 8) * 2;

    auto issueB = [&](int c) {
        const int kb = c * 32 + sg * 8;
        const uint32_t bo = (uint32_t)(c & 1) * ABUF;
        cpa16(sb + 4 * ABUF + bo + d0, Bh + (size_t)wn0 * HDIM + kb);
        cpa16(sb + 4 * ABUF + bo + d1, Bh + (size_t)wn1 * HDIM + kb);
        cpa16(sb + 6 * ABUF + bo + d0, Bl + (size_t)wn0 * HDIM + kb);
        cpa16(sb + 6 * ABUF + bo + d1, Bl + (size_t)wn1 * HDIM + kb);
        asm volatile("cp.async.commit_group;");
    };

    float4 ar[4];
    auto loadA = [&](int c) {
        const int kb = c * 32 + sg * 8;
        ar[0] = *(const float4*)(Hin + (size_t)gr0 * HDIM + kb);
        ar[1] = *(const float4*)(Hin + (size_t)gr0 * HDIM + kb + 4);
        ar[2] = *(const float4*)(Hin + (size_t)gr1 * HDIM + kb);
        ar[3] = *(const float4*)(Hin + (size_t)gr1 * HDIM + kb + 4);
    };
    auto stageA = [&](int c) {
        const int kb = c * 32 + sg * 8;
        const uint32_t bo = (uint32_t)(c & 1) * ABUF;
        float s[8], sh[8];
#pragma unroll
        for (int j = 0; j < 8; j++) { s[j] = sS[kb + j]; sh[j] = sSh[kb + j]; }
        const float* av = (const float*)ar;
        uint32_t hiw[4], low[4];
#pragma unroll
        for (int rr = 0; rr < 2; rr++) {
            __nv_bfloat16 hb[8], lb[8];
#pragma unroll
            for (int j = 0; j < 8; j++) {
                float v = fmaf(av[rr * 8 + j], s[j], sh[j]);
                if (do_bn) v = fmaxf(v, 0.f);
                hb[j] = __float2bfloat16(v);
                lb[j] = __float2bfloat16(v - __bfloat162float(hb[j]));
            }
#pragma unroll
            for (int j = 0; j < 4; j++) {
                hiw[j] = bf2pack(hb[2 * j], hb[2 * j + 1]);
                low[j] = bf2pack(lb[2 * j], lb[2 * j + 1]);
            }
            const uint32_t dd = rr ? d1 : d0;
            *(uint4*)(dsm + bo + dd)            = *(uint4*)hiw;
            *(uint4*)(dsm + 2 * ABUF + bo + dd) = *(uint4*)low;
        }
    };

    // ldmatrix lane offsets
    const int li = lane & 7;
    const int lb_ = (lane >> 3) & 1;
    const int lc = (lane >> 4) & 1;
    uint32_t aoff[2], boff[4];
#pragma unroll
    for (int mf = 0; mf < 2; mf++)
        aoff[mf] = (uint32_t)((wm * 32 + mf * 16 + lb_ * 8 + li) * SROW + lc * 8) * 2;
#pragma unroll
    for (int nf = 0; nf < 4; nf++)
        boff[nf] = (uint32_t)((wn * 64 + nf * 16 + lc * 8 + li) * SROW + lb_ * 8) * 2;

    float acc[2][8][4];
#pragma unroll
    for (int i = 0; i < 2; i++)
#pragma unroll
        for (int j = 0; j < 8; j++)
#pragma unroll
            for (int k = 0; k < 4; k++) acc[i][j][k] = 0.f;

    issueB(0);
    loadA(0);
    __syncthreads();        // sS/sSh ready
    stageA(0);

    for (int c = 0; c < 8; c++) {
        asm volatile("cp.async.wait_group 0;" ::: "memory");
        __syncthreads();    // A(c)+B(c) visible; all MMA(c-1) reads done
        if (c < 7) { issueB(c + 1); loadA(c + 1); }

        const uint32_t bo  = (uint32_t)(c & 1) * ABUF;
        const uint32_t bAh = sb + bo;
        const uint32_t bAl = sb + 2 * ABUF + bo;
        const uint32_t bBh = sb + 4 * ABUF + bo;
        const uint32_t bBl = sb + 6 * ABUF + bo;
#pragma unroll
        for (int ks = 0; ks < 2; ks++) {
            const uint32_t kadd = ks * 32;
            uint32_t A0h[4], A1h[4], A0l[4], A1l[4];
            ldm_x4(A0h[0], A0h[1], A0h[2], A0h[3], bAh + aoff[0] + kadd);
            ldm_x4(A1h[0], A1h[1], A1h[2], A1h[3], bAh + aoff[1] + kadd);
            ldm_x4(A0l[0], A0l[1], A0l[2], A0l[3], bAl + aoff[0] + kadd);
            ldm_x4(A1l[0], A1l[1], A1l[2], A1l[3], bAl + aoff[1] + kadd);
#pragma unroll
            for (int nf = 0; nf < 4; nf++) {
                uint32_t bh[4], bl[4];
                ldm_x4(bh[0], bh[1], bh[2], bh[3], bBh + boff[nf] + kadd);
                ldm_x4(bl[0], bl[1], bl[2], bl[3], bBl + boff[nf] + kadd);
                mma_bf16(acc[0][nf * 2 + 0], A0h, bh[0], bh[1]);
                mma_bf16(acc[0][nf * 2 + 0], A0h, bl[0], bl[1]);
                mma_bf16(acc[0][nf * 2 + 0], A0l, bh[0], bh[1]);
                mma_bf16(acc[0][nf * 2 + 1], A0h, bh[2], bh[3]);
                mma_bf16(acc[0][nf * 2 + 1], A0h, bl[2], bl[3]);
                mma_bf16(acc[0][nf * 2 + 1], A0l, bh[2], bh[3]);
                mma_bf16(acc[1][nf * 2 + 0], A1h, bh[0], bh[1]);
                mma_bf16(acc[1][nf * 2 + 0], A1h, bl[0], bl[1]);
                mma_bf16(acc[1][nf * 2 + 0], A1l, bh[0], bh[1]);
                mma_bf16(acc[1][nf * 2 + 1], A1h, bh[2], bh[3]);
                mma_bf16(acc[1][nf * 2 + 1], A1h, bl[2], bl[3]);
                mma_bf16(acc[1][nf * 2 + 1], A1l, bh[2], bh[3]);
            }
        }
        if (c < 7) stageA(c + 1);   // other buffer; last read at MMA(c-1)
    }

    // epilogue: C[r, c] = (acc + bias[c]) * dinv[r]
    const int qr = lane >> 2;
    const int qc = (lane & 3) * 2;
#pragma unroll
    for (int mf = 0; mf < 2; mf++) {
        int rr0 = brow + wm * 32 + mf * 16 + qr;
        int rr1 = rr0 + 8;
        float dv0 = (rr0 < M) ? dinv[rr0] : 0.f;
        float dv1 = (rr1 < M) ? dinv[rr1] : 0.f;
#pragma unroll
        for (int nf = 0; nf < 8; nf++) {
            int cc = bcol + wn * 64 + nf * 8 + qc;
            float b0 = bias[cc], b1 = bias[cc + 1];
            if (rr0 < M)
                *(float2*)(C + (size_t)rr0 * HDIM + cc) =
                    make_float2((acc[mf][nf][0] + b0) * dv0,
                                (acc[mf][nf][1] + b1) * dv0);
            if (rr1 < M)
                *(float2*)(C + (size_t)rr1 * HDIM + cc) =
                    make_float2((acc[mf][nf][2] + b0) * dv1,
                                (acc[mf][nf][3] + b1) * dv1);
        }
    }
}

// ---------------- CSR aggregation + fused BN stats --------------------------
__global__ __launch_bounds__(256)
void agg_kernel(const int* __restrict__ rowptr, const int* __restrict__ csr,
                const float* __restrict__ dinv, const float* __restrict__ tp,
                float* __restrict__ h, float* gsum, float* gsq) {
    __shared__ float s_sum[HDIM];
    __shared__ float s_sq[HDIM];
    int tid  = threadIdx.x;
    int lane = tid & 31;
    int warp = tid >> 5;
    int gw   = blockIdx.x * 8 + warp;
    int nw   = gridDim.x * 8;

    s_sum[tid] = 0.f;
    s_sq[tid]  = 0.f;

    float ssum[8], ssq[8];
#pragma unroll
    for (int i = 0; i < 8; i++) { ssum[i] = 0.f; ssq[i] = 0.f; }

    for (int v = gw; v < N_NODES; v += nw) {
        const float4* self = (const float4*)(tp + (size_t)v * HDIM);
        float4 a0 = self[lane];
        float4 a1 = self[lane + 32];
        int beg = rowptr[v], end = rowptr[v + 1];
        int e = beg;
        for (; e + 1 < end; e += 2) {
            int s0 = csr[e], s1 = csr[e + 1];
            const float4* r0 = (const float4*)(tp + (size_t)s0 * HDIM);
            const float4* r1 = (const float4*)(tp + (size_t)s1 * HDIM);
            float4 v00 = r0[lane], v01 = r0[lane + 32];
            float4 v10 = r1[lane], v11 = r1[lane + 32];
            a0.x += v00.x + v10.x; a0.y += v00.y + v10.y;
            a0.z += v00.z + v10.z; a0.w += v00.w + v10.w;
            a1.x += v01.x + v11.x; a1.y += v01.y + v11.y;
            a1.z += v01.z + v11.z; a1.w += v01.w + v11.w;
        }
        if (e < end) {
            int s0 = csr[e];
            const float4* r0 = (const float4*)(tp + (size_t)s0 * HDIM);
            float4 v00 = r0[lane], v01 = r0[lane + 32];
            a0.x += v00.x; a0.y += v00.y; a0.z += v00.z; a0.w += v00.w;
            a1.x += v01.x; a1.y += v01.y; a1.z += v01.z; a1.w += v01.w;
        }
        float dv = dinv[v];
        a0.x *= dv; a0.y *= dv; a0.z *= dv; a0.w *= dv;
        a1.x *= dv; a1.y *= dv; a1.z *= dv; a1.w *= dv;
        float4* hrow = (float4*)(h + (size_t)v * HDIM);
        hrow[lane]      = a0;
        hrow[lane + 32] = a1;
        ssum[0] += a0.x; ssum[1] += a0.y; ssum[2] += a0.z; ssum[3] += a0.w;
        ssum[4] += a1.x; ssum[5] += a1.y; ssum[6] += a1.z; ssum[7] += a1.w;
        ssq[0] += a0.x * a0.x; ssq[1] += a0.y * a0.y;
        ssq[2] += a0.z * a0.z; ssq[3] += a0.w * a0.w;
        ssq[4] += a1.x * a1.x; ssq[5] += a1.y * a1.y;
        ssq[6] += a1.z * a1.z; ssq[7] += a1.w * a1.w;
    }
    __syncthreads();
#pragma unroll
    for (int k = 0; k < 4; k++) {
        atomicAdd(&s_sum[lane * 4 + k], ssum[k]);
        atomicAdd(&s_sum[128 + lane * 4 + k], ssum[4 + k]);
        atomicAdd(&s_sq[lane * 4 + k], ssq[k]);
        atomicAdd(&s_sq[128 + lane * 4 + k], ssq[4 + k]);
    }
    __syncthreads();
    atomicAdd(&gsum[tid], s_sum[tid]);
    atomicAdd(&gsq[tid], s_sq[tid]);
}

// ---------------- combine: comb = sum_l w_l relu(bn_l(hist_l)) --------------
__global__ __launch_bounds__(256)
void combine_kernel(const float* __restrict__ hist,
                    const float* __restrict__ sums, const float* __restrict__ sqs,
                    const float* __restrict__ gamma, const float* __restrict__ beta,
                    const float* __restrict__ w, float* __restrict__ comb) {
    __shared__ float sS[L_LAYERS][HDIM];
    __shared__ float sSh[L_LAYERS][HDIM];
    __shared__ float sw[L_LAYERS];
    int t = threadIdx.x;
    if (t < L_LAYERS) sw[t] = w[t];
#pragma unroll
    for (int l = 0; l < L_LAYERS; l++) {
        float mu  = sums[l * HDIM + t] * (1.0f / N_NODES);
        float var = sqs[l * HDIM + t] * (1.0f / N_NODES) - mu * mu;
        float s = gamma[l * HDIM + t] * rsqrtf(var + BN_EPS);
        sS[l][t] = s;
        sSh[l][t] = beta[l * HDIM + t] - mu * s;
    }
    __syncthreads();
    for (int r = blockIdx.x; r < N_NODES; r += gridDim.x) {
        float a = 0.f;
#pragma unroll
        for (int l = 0; l < L_LAYERS; l++) {
            float v = fmaf(hist[(size_t)l * N_NODES * HDIM + (size_t)r * HDIM + t],
                           sS[l][t], sSh[l][t]);
            a = fmaf(sw[l], fmaxf(v, 0.f), a);
        }
        comb[(size_t)r * HDIM + t] = a;
    }
}

// ---------------- output FC + fused log-softmax -----------------------------
// C_OUT=112 <= BN=128: one CTA covers all classes for its 128 rows.
__global__ __launch_bounds__(256, 2)
void out_gemm_kernel(const float* __restrict__ A, const float* __restrict__ B,
                     const float* __restrict__ bias, float* __restrict__ out,
                     int M) {
    const int Nc = C_OUT;
    const int K = HDIM;
    __shared__ float As[2][BK][BM + 4];
    __shared__ float Bs[2][BK][BN];
    const int tid  = threadIdx.x;
    const int tRow = tid >> 4;
    const int tCol = tid & 15;
    const int brow = blockIdx.y * BM;
    const int am0 = tid >> 2;
    const int am1 = (tid + 256) >> 2;
    const int ak  = (tid & 3) * 4;
    const int arow0 = min(brow + am0, M - 1);
    const int arow1 = min(brow + am1, M - 1);
    const int bk0 = tid >> 5;
    const int bk1 = bk0 + 8;
    const int bnx = (tid & 31) * 4;
    const bool bok = (bnx + 3) < Nc;
    const int bcl  = bok ? bnx : 0;

    unsigned long long acc[8][4];
#pragma unroll
    for (int i = 0; i < 8; i++)
#pragma unroll
        for (int j = 0; j < 4; j++) acc[i][j] = 0ull;

    float4 aR0, aR1, bR0, bR1;
    const float4 z4 = make_float4(0.f, 0.f, 0.f, 0.f);
    aR0 = *(const float4*)(A + (size_t)arow0 * K + ak);
    aR1 = *(const float4*)(A + (size_t)arow1 * K + ak);
    bR0 = bok ? *(const float4*)(B + (size_t)bk0 * Nc + bcl) : z4;
    bR1 = bok ? *(const float4*)(B + (size_t)bk1 * Nc + bcl) : z4;
    As[0][ak + 0][am0] = aR0.x; As[0][ak + 1][am0] = aR0.y;
    As[0][ak + 2][am0] = aR0.z; As[0][ak + 3][am0] = aR0.w;
    As[0][ak + 0][am1] = aR1.x; As[0][ak + 1][am1] = aR1.y;
    As[0][ak + 2][am1] = aR1.z; As[0][ak + 3][am1] = aR1.w;
    *(float4*)&Bs[0][bk0][bnx] = bR0;
    *(float4*)&Bs[0][bk1][bnx] = bR1;
    __syncthreads();

    const int nt = K / BK;
    for (int kt = 0; kt < nt; kt++) {
        const int buf = kt & 1;
        const int nxt = kt + 1;
        if (nxt < nt) {
            const int k0 = nxt * BK;
            aR0 = *(const float4*)(A + (size_t)arow0 * K + k0 + ak);
            aR1 = *(const float4*)(A + (size_t)arow1 * K + k0 + ak);
            bR0 = bok ? *(const float4*)(B + (size_t)(k0 + bk0) * Nc + bcl) : z4;
            bR1 = bok ? *(const float4*)(B + (size_t)(k0 + bk1) * Nc + bcl) : z4;
        }
#pragma unroll
        for (int k = 0; k < BK; k++) {
            float4 a0 = *(const float4*)&As[buf][k][tRow * 4];
            float4 a1 = *(const float4*)&As[buf][k][64 + tRow * 4];
            float4 b0 = *(const float4*)&Bs[buf][k][tCol * 4];
            float4 b1 = *(const float4*)&Bs[buf][k][64 + tCol * 4];
            unsigned long long bb[4] = {pk2(b0.x, b0.y), pk2(b0.z, b0.w),
                                        pk2(b1.x, b1.y), pk2(b1.z, b1.w)};
            float av[8] = {a0.x, a0.y, a0.z, a0.w, a1.x, a1.y, a1.z, a1.w};
#pragma unroll
            for (int i = 0; i < 8; i++) {
                unsigned long long ap = pk2(av[i], av[i]);
#pragma unroll
                for (int j = 0; j < 4; j++) ffma2(acc[i][j], ap, bb[j]);
            }
        }
        if (nxt < nt) {
            const int nb = nxt & 1;
            As[nb][ak + 0][am0] = aR0.x; As[nb][ak + 1][am0] = aR0.y;
            As[nb][ak + 2][am0] = aR0.z; As[nb][ak + 3][am0] = aR0.w;
            As[nb][ak + 0][am1] = aR1.x; As[nb][ak + 1][am1] = aR1.y;
            As[nb][ak + 2][am1] = aR1.z; As[nb][ak + 3][am1] = aR1.w;
            *(float4*)&Bs[nb][bk0][bnx] = bR0;
            *(float4*)&Bs[nb][bk1][bnx] = bR1;
        }
        __syncthreads();
    }

    // fused log-softmax epilogue: row r's 112 logits live across the 16
    // threads sharing tRow (lanes (tRow&1)*16 + 0..15) — shfl-reduce.
#pragma unroll
    for (int ih = 0; ih < 2; ih++) {
#pragma unroll
        for (int i = 0; i < 4; i++) {
            int r = brow + ih * 64 + tRow * 4 + i;
            float vals[8];
#pragma unroll
            for (int jh = 0; jh < 2; jh++) {
                float e0, e1, e2, e3;
                upk2(e0, e1, acc[ih * 4 + i][jh * 2 + 0]);
                upk2(e2, e3, acc[ih * 4 + i][jh * 2 + 1]);
                int c = jh * 64 + tCol * 4;
                vals[jh * 4 + 0] = (c + 0 < Nc) ? e0 + bias[c + 0] : -1e30f;
                vals[jh * 4 + 1] = (c + 1 < Nc) ? e1 + bias[c + 1] : -1e30f;
                vals[jh * 4 + 2] = (c + 2 < Nc) ? e2 + bias[c + 2] : -1e30f;
                vals[jh * 4 + 3] = (c + 3 < Nc) ? e3 + bias[c + 3] : -1e30f;
            }
            float m = vals[0];
#pragma unroll
            for (int j = 1; j < 8; j++) m = fmaxf(m, vals[j]);
#pragma unroll
            for (int off = 8; off >= 1; off >>= 1)
                m = fmaxf(m, __shfl_xor_sync(0xffffffffu, m, off));
            float s = 0.f;
#pragma unroll
            for (int j = 0; j < 8; j++) s += expf(vals[j] - m);
#pragma unroll
            for (int off = 8; off >= 1; off >>= 1)
                s += __shfl_xor_sync(0xffffffffu, s, off);
            float lse = m + logf(s);
            if (r < M) {
#pragma unroll
                for (int jh = 0; jh < 2; jh++) {
                    int c = jh * 64 + tCol * 4;
#pragma unroll
                    for (int j = 0; j < 4; j++)
                        if (c + j < Nc)
                            out[(size_t)r * Nc + c + j] = vals[jh * 4 + j] - lse;
                }
            }
        }
    }
}

// ---------------- host launcher ---------------------------------------------
extern "C" void kernel_launch(void* const* d_in, const int* in_sizes, int n_in,
                              void* d_out, int out_size) {
    const float* x       = (const float*)d_in[0];
    const int*   e1      = (const int*)  d_in[1];
    const int*   e2      = (const int*)  d_in[2];
    const float* in_W    = (const float*)d_in[3];
    const float* in_b    = (const float*)d_in[4];
    const float* convW   = (const float*)d_in[5];
    const float* convB   = (const float*)d_in[6];
    const float* bng     = (const float*)d_in[7];
    const float* bnb     = (const float*)d_in[8];
    const float* out_W   = (const float*)d_in[9];
    const float* out_b   = (const float*)d_in[10];
    const float* layer_w = (const float*)d_in[11];
    float* out = (float*)d_out;

    float *p_h0, *p_t, *p_hist, *p_comb, *p_dinv1, *p_dinv2, *p_sums, *p_sqs, *p_w;
    __nv_bfloat16 *p_wth, *p_wtl;
    int *p_cnt1, *p_cnt2, *p_rp1, *p_rp2, *p_cur1, *p_cur2, *p_csr1, *p_csr2;
    cudaGetSymbolAddress((void**)&p_h0, g_h0);
    cudaGetSymbolAddress((void**)&p_t, g_t);
    cudaGetSymbolAddress((void**)&p_hist, g_hist);
    cudaGetSymbolAddress((void**)&p_comb, g_comb);
    cudaGetSymbolAddress((void**)&p_wth, g_wth);
    cudaGetSymbolAddress((void**)&p_wtl, g_wtl);
    cudaGetSymbolAddress((void**)&p_dinv1, g_dinv1);
    cudaGetSymbolAddress((void**)&p_dinv2, g_dinv2);
    cudaGetSymbolAddress((void**)&p_sums, g_sums);
    cudaGetSymbolAddress((void**)&p_sqs, g_sqs);
    cudaGetSymbolAddress((void**)&p_w, g_w);
    cudaGetSymbolAddress((void**)&p_cnt1, g_cnt1);
    cudaGetSymbolAddress((void**)&p_cnt2, g_cnt2);
    cudaGetSymbolAddress((void**)&p_rp1, g_rp1);
    cudaGetSymbolAddress((void**)&p_rp2, g_rp2);
    cudaGetSymbolAddress((void**)&p_cur1, g_cur1);
    cudaGetSymbolAddress((void**)&p_cur2, g_cur2);
    cudaGetSymbolAddress((void**)&p_csr1, g_csr1);
    cudaGetSymbolAddress((void**)&p_csr2, g_csr2);

    cudaFuncSetAttribute(mma_gemm_kernel,
                         cudaFuncAttributeMaxDynamicSharedMemorySize, MG_SMEM);

    const int nThr = 256;
    const int nbN  = (N_NODES + nThr - 1) / nThr;
    const int nbE  = (E_EDGES + nThr - 1) / nThr;
    const int nbW  = (L_LAYERS * HDIM * HDIM + nThr - 1) / nThr;
    const dim3 gemmH(HDIM / BN, (N_NODES + BM - 1) / BM);
    const dim3 outGrid(1, (N_NODES + BM - 1) / BM);
    const dim3 mmaGrid(2, (N_NODES + 127) / 128);
    const int aggBlocks = 1480;
    const size_t NH = (size_t)N_NODES * HDIM;

    prep_kernel<<<nbW, nThr>>>(convW, layer_w, p_wth, p_wtl, p_sums, p_sqs, p_w);
    gemm_bias_kernel<<<gemmH, nThr>>>(x, in_W, in_b, p_h0, N_NODES, HDIM, F_INPUT);

    zero2_kernel<<<nbN, nThr>>>(p_cnt1, p_cnt2);
    hist2_kernel<<<nbE, nThr>>>(e1 + E_EDGES, e2 + E_EDGES, p_cnt1, p_cnt2);
    scan2_kernel<<<2, 1024>>>(p_cnt1, p_cnt2, p_rp1, p_rp2);
    dinvcur2_kernel<<<nbN, nThr>>>(p_rp1, p_rp2, p_dinv1, p_dinv2, p_cur1, p_cur2);
    fill2_kernel<<<nbE, nThr>>>(e1, e2, p_cur1, p_cur2, p_csr1, p_csr2);

    for (int l = 0; l < L_LAYERS; l++) {
        const int*   rp   = (l < L_LAYERS / 2) ? p_rp1 : p_rp2;
        const int*   csr  = (l < L_LAYERS / 2) ? p_csr1 : p_csr2;
        const float* dinv = (l < L_LAYERS / 2) ? p_dinv1 : p_dinv2;
        const float* Hin  = (l == 0) ? p_h0 : p_hist + (size_t)(l - 1) * NH;
        const float* bs   = (l == 0) ? p_sums : p_sums + (l - 1) * HDIM;
        const float* bq   = (l == 0) ? p_sqs  : p_sqs + (l - 1) * HDIM;
        const float* bg   = (l == 0) ? bng : bng + (l - 1) * HDIM;
        const float* bb   = (l == 0) ? bnb : bnb + (l - 1) * HDIM;

        mma_gemm_kernel<<<mmaGrid, nThr, MG_SMEM>>>(
            Hin, bs, bq, bg, bb, (l > 0) ? 1 : 0,
            p_wth + (size_t)l * HDIM * HDIM, p_wtl + (size_t)l * HDIM * HDIM,
            convB + l * HDIM, dinv, p_t, N_NODES);
        agg_kernel<<<aggBlocks, nThr>>>(rp, csr, dinv, p_t,
                                        p_hist + (size_t)l * NH,
                                        p_sums + l * HDIM, p_sqs + l * HDIM);
    }

    combine_kernel<<<2048, nThr>>>(p_hist, p_sums, p_sqs, bng, bnb, p_w, p_comb);
    out_gemm_kernel<<<outGrid, nThr>>>(p_comb, out_W, out_b, out, N_NODES);
}